// round 11
// baseline (speedup 1.0000x reference)
#include <cuda_runtime.h>
#include <cuda_bf16.h>
#include <cstdint>

#define SCALE       0.35355339059327373f   // 64^(-1/4)
#define INV_SQRT_M  0.08838834764831843f   // 1/sqrt(128)
#define EPS_PHI     1e-4f
#define EPS_DEN     1e-6f

#define BH    64        // B*H = 4*16
#define Nn    4096
#define Dd    64
#define Mm    128
#define CH    128       // chunk length
#define NC    32        // chunks per head
#define NTOK  (BH*Nn)   // 262144
#define NBT   (NTOK/CH) // 2048 token-chunks

typedef unsigned long long u64;
typedef unsigned int u32;
typedef unsigned short u16;

// ---------------- packed fp32x2 (K2) ----------------
__device__ __forceinline__ u64 pk2(float x, float y) {
    u64 r; asm("mov.b64 %0, {%1,%2};" : "=l"(r) : "f"(x), "f"(y)); return r;
}
__device__ __forceinline__ void upk2(u64 p, float& x, float& y) {
    asm("mov.b64 {%0,%1}, %2;" : "=f"(x), "=f"(y) : "l"(p));
}
__device__ __forceinline__ u64 ffma2(u64 a, u64 b, u64 c) {
    u64 d; asm("fma.rn.f32x2 %0, %1, %2, %3;" : "=l"(d) : "l"(a), "l"(b), "l"(c)); return d;
}

// ---------------- warp MMA helpers ----------------
__device__ __forceinline__ u32 s2u(const void* p) {
    u32 a; asm("{ .reg .u64 t; cvta.to.shared.u64 t, %1; cvt.u32.u64 %0, t; }"
               : "=r"(a) : "l"(p));
    return a;
}
__device__ __forceinline__ void ldsm4(u32& r0, u32& r1, u32& r2, u32& r3, u32 addr) {
    asm volatile("ldmatrix.sync.aligned.m8n8.x4.shared.b16 {%0,%1,%2,%3}, [%4];"
                 : "=r"(r0), "=r"(r1), "=r"(r2), "=r"(r3) : "r"(addr));
}
__device__ __forceinline__ void ldsm2(u32& r0, u32& r1, u32 addr) {
    asm volatile("ldmatrix.sync.aligned.m8n8.x2.shared.b16 {%0,%1}, [%2];"
                 : "=r"(r0), "=r"(r1) : "r"(addr));
}
__device__ __forceinline__ void mma16816(float* d, u32 a0, u32 a1, u32 a2, u32 a3,
                                         u32 b0, u32 b1) {
    asm volatile("mma.sync.aligned.m16n8k16.row.col.f32.bf16.bf16.f32 "
                 "{%0,%1,%2,%3}, {%4,%5,%6,%7}, {%8,%9}, {%0,%1,%2,%3};"
                 : "+f"(d[0]), "+f"(d[1]), "+f"(d[2]), "+f"(d[3])
                 : "r"(a0), "r"(a1), "r"(a2), "r"(a3), "r"(b0), "r"(b1));
}

// bf16 split
__device__ __forceinline__ u16 bf16h(float x) {
    u16 u; asm("cvt.rn.bf16.f32 %0, %1;" : "=h"(u) : "f"(x)); return u;
}
__device__ __forceinline__ float bf2f(u16 u) {
    float f; asm("cvt.f32.bf16 %0, %1;" : "=f"(f) : "h"(u)); return f;
}
__device__ __forceinline__ void split2(float x, u16& h, u16& l) {
    h = bf16h(x); l = bf16h(x - bf2f(h));
}

// Tile row strides (bytes): 136-half rows (K4), 72-half rows (K1)
#define SR  272
#define SR1 144
__device__ __forceinline__ u32 a_addr_s(u32 base, int m0, int k0, int lane, int srb) {
    int r  = m0 + (lane & 7) + ((lane >> 3) & 1) * 8;
    int kc = k0 + (lane >> 4) * 8;
    return base + r * srb + kc * 2;
}
__device__ __forceinline__ u32 b_addr_s(u32 base, int n0, int k0, int lane, int srb) {
    int r  = n0 + (lane & 7);
    int kc = k0 + ((lane >> 3) & 1) * 8;
    return base + r * srb + kc * 2;
}
// paired-tile B address for ldmatrix.x4: matrices {nt:k0, nt:k0+8, nt+1:k0, nt+1:k0+8}
__device__ __forceinline__ u32 b2_addr_s(u32 base, int n0, int k0, int lane, int srb) {
    int l8 = lane & 7, sel = lane >> 3;
    int r  = n0 + ((sel & 2) ? 8 : 0) + l8;
    int kc = k0 + ((sel & 1) ? 8 : 0);
    return base + r * srb + kc * 2;
}
__device__ __forceinline__ u32 a_addr(u32 base, int m0, int k0, int lane) {
    return a_addr_s(base, m0, k0, lane, SR);
}
__device__ __forceinline__ u32 b_addr(u32 base, int n0, int k0, int lane) {
    return b_addr_s(base, n0, k0, lane, SR);
}
__device__ __forceinline__ u32 b2_addr(u32 base, int n0, int k0, int lane) {
    return b2_addr_s(base, n0, k0, lane, SR);
}

// Scratch
__device__ float d_phiq[(size_t)NTOK*Mm];
__device__ float d_phik[(size_t)NTOK*Mm];   // lp, then phi_k after K2
__device__ float d_S[(size_t)BH*NC*Mm*Dd];
__device__ float d_zz[BH*NC*Mm];
__device__ float d_bmax[NBT];
__device__ float d_gmax;

// ---------------------------------------------------------------------------
// K1 (warp-MMA): proj[128,128] = (x*scale)[128,64] @ omega^T, bf16 split.
// ---------------------------------------------------------------------------
#define P_SSP 0
#define P_SS  8192
#define P_RED 8704
#define P_XH  9728
#define P_XL  (P_XH + 18432)
#define P_OH  (P_XL + 18432)
#define P_OL  (P_OH + 18432)
#define SM1T  (P_OL + 18432)   // 83456 B

__global__ __launch_bounds__(256) void k_proj_mma(const float* __restrict__ qg,
                                                  const float* __restrict__ kg,
                                                  const float* __restrict__ omg) {
    extern __shared__ char smc[];
    const u32 sb = s2u(smc);
    float* ssp = (float*)(smc + P_SSP);
    float* ss  = (float*)(smc + P_SS);
    float* red = (float*)(smc + P_RED);

    const int bid = blockIdx.x;
    const bool isq = bid < NBT;
    const int tb  = isq ? bid : bid - NBT;
    const float* xg = (isq ? qg : kg) + (size_t)tb * CH * Dd;
    const int tid = threadIdx.x, wid = tid >> 5, lane = tid & 31;

    #pragma unroll
    for (int it = 0; it < 8; it++) {
        int f4g = it*256 + tid;
        int r = f4g >> 4, p = f4g & 15, c4 = p * 4;
        u32 off = (u32)r * SR1 + (u32)c4 * 2;
        float4 t = *reinterpret_cast<const float4*>(xg + r*Dd + c4);
        t.x *= SCALE; t.y *= SCALE; t.z *= SCALE; t.w *= SCALE;
        ssp[f4g] = t.x*t.x + t.y*t.y + t.z*t.z + t.w*t.w;
        u16 h0,l0,h1,l1,h2,l2,h3,l3;
        split2(t.x,h0,l0); split2(t.y,h1,l1); split2(t.z,h2,l2); split2(t.w,h3,l3);
        *(u32*)(smc+P_XH+off)   = (u32)h0 | ((u32)h1<<16);
        *(u32*)(smc+P_XH+off+4) = (u32)h2 | ((u32)h3<<16);
        *(u32*)(smc+P_XL+off)   = (u32)l0 | ((u32)l1<<16);
        *(u32*)(smc+P_XL+off+4) = (u32)l2 | ((u32)l3<<16);
        float4 w = *reinterpret_cast<const float4*>(omg + (size_t)f4g * 4);
        split2(w.x,h0,l0); split2(w.y,h1,l1); split2(w.z,h2,l2); split2(w.w,h3,l3);
        *(u32*)(smc+P_OH+off)   = (u32)h0 | ((u32)h1<<16);
        *(u32*)(smc+P_OH+off+4) = (u32)h2 | ((u32)h3<<16);
        *(u32*)(smc+P_OL+off)   = (u32)l0 | ((u32)l1<<16);
        *(u32*)(smc+P_OL+off+4) = (u32)l2 | ((u32)l3<<16);
    }
    __syncthreads();
    if (tid < 128) {
        float s = 0.f;
        #pragma unroll
        for (int j = 0; j < 16; j++) s += ssp[tid*16 + j];
        ss[tid] = 0.5f * s;
    }
    __syncthreads();

    const int i0 = wid * 16;
    float acc[16][4];
    #pragma unroll
    for (int nt = 0; nt < 16; nt++)
        #pragma unroll
        for (int e = 0; e < 4; e++) acc[nt][e] = 0.f;

    #pragma unroll
    for (int kk = 0; kk < 4; kk++) {
        int k0 = kk * 16;
        u32 xh0,xh1,xh2,xh3, xl0,xl1,xl2,xl3;
        ldsm4(xh0,xh1,xh2,xh3, a_addr_s(sb+P_XH, i0, k0, lane, SR1));
        ldsm4(xl0,xl1,xl2,xl3, a_addr_s(sb+P_XL, i0, k0, lane, SR1));
        #pragma unroll
        for (int np = 0; np < 8; np++) {        // tile pair (2np, 2np+1)
            u32 oh0,oh1,oh2,oh3, ol0,ol1,ol2,ol3;
            ldsm4(oh0,oh1,oh2,oh3, b2_addr_s(sb+P_OH, np*16, k0, lane, SR1));
            ldsm4(ol0,ol1,ol2,ol3, b2_addr_s(sb+P_OL, np*16, k0, lane, SR1));
            mma16816(acc[2*np],   xh0,xh1,xh2,xh3, oh0,oh1);
            mma16816(acc[2*np],   xh0,xh1,xh2,xh3, ol0,ol1);
            mma16816(acc[2*np],   xl0,xl1,xl2,xl3, oh0,oh1);
            mma16816(acc[2*np+1], xh0,xh1,xh2,xh3, oh2,oh3);
            mma16816(acc[2*np+1], xh0,xh1,xh2,xh3, ol2,ol3);
            mma16816(acc[2*np+1], xl0,xl1,xl2,xl3, oh2,oh3);
        }
    }

    const int m1 = i0 + (lane >> 2);
    const int m2 = m1 + 8;
    const size_t tok0 = (size_t)tb * CH;

    if (isq) {
        float rm1 = -3.0e38f, rm2 = -3.0e38f;
        #pragma unroll
        for (int nt = 0; nt < 16; nt++) {
            rm1 = fmaxf(rm1, fmaxf(acc[nt][0], acc[nt][1]));
            rm2 = fmaxf(rm2, fmaxf(acc[nt][2], acc[nt][3]));
        }
        rm1 = fmaxf(rm1, __shfl_xor_sync(0xFFFFFFFFu, rm1, 1));
        rm1 = fmaxf(rm1, __shfl_xor_sync(0xFFFFFFFFu, rm1, 2));
        rm2 = fmaxf(rm2, __shfl_xor_sync(0xFFFFFFFFu, rm2, 1));
        rm2 = fmaxf(rm2, __shfl_xor_sync(0xFFFFFFFFu, rm2, 2));
        float* og = d_phiq + tok0 * Mm;
        #pragma unroll
        for (int nt = 0; nt < 16; nt++) {
            int jj = nt*8 + 2*(lane & 3);
            float2 t1, t2;
            t1.x = __expf(acc[nt][0]-rm1)*INV_SQRT_M + EPS_PHI;
            t1.y = __expf(acc[nt][1]-rm1)*INV_SQRT_M + EPS_PHI;
            t2.x = __expf(acc[nt][2]-rm2)*INV_SQRT_M + EPS_PHI;
            t2.y = __expf(acc[nt][3]-rm2)*INV_SQRT_M + EPS_PHI;
            *reinterpret_cast<float2*>(og + (size_t)m1*Mm + jj) = t1;
            *reinterpret_cast<float2*>(og + (size_t)m2*Mm + jj) = t2;
        }
    } else {
        const float s1 = ss[m1], s2 = ss[m2];
        float bm = -3.0e38f;
        float* og = d_phik + tok0 * Mm;
        #pragma unroll
        for (int nt = 0; nt < 16; nt++) {
            int jj = nt*8 + 2*(lane & 3);
            float2 t1, t2;
            t1.x = acc[nt][0] - s1; t1.y = acc[nt][1] - s1;
            t2.x = acc[nt][2] - s2; t2.y = acc[nt][3] - s2;
            bm = fmaxf(bm, fmaxf(fmaxf(t1.x, t1.y), fmaxf(t2.x, t2.y)));
            *reinterpret_cast<float2*>(og + (size_t)m1*Mm + jj) = t1;
            *reinterpret_cast<float2*>(og + (size_t)m2*Mm + jj) = t2;
        }
        red[tid] = bm;
        __syncthreads();
        for (int s = 128; s > 0; s >>= 1) {
            if (tid < s) red[tid] = fmaxf(red[tid], red[tid+s]);
            __syncthreads();
        }
        if (tid == 0) d_bmax[tb] = red[0];
    }
}

__global__ __launch_bounds__(256) void k_gmax() {
    __shared__ float red[256];
    const int tid = threadIdx.x;
    float m = -3.0e38f;
    for (int i = tid; i < NBT; i += 256) m = fmaxf(m, d_bmax[i]);
    red[tid] = m;
    __syncthreads();
    for (int s = 128; s > 0; s >>= 1) {
        if (tid < s) red[tid] = fmaxf(red[tid], red[tid+s]);
        __syncthreads();
    }
    if (tid == 0) d_gmax = red[0];
}

// ---------------------------------------------------------------------------
// K2: phi_k = exp(lp-gmax)/sqrt(M)+eps (written back); chunk sums (R6 scalar)
// ---------------------------------------------------------------------------
__global__ __launch_bounds__(256) void k_phik_sums(const float* __restrict__ vg) {
    extern __shared__ float sm[];
    float* phis = sm;            // [128][128]
    float* vs   = sm + 128*128;  // [128][64]
    const int bid = blockIdx.x;
    const int bh = bid >> 5, c = bid & 31;
    const size_t tok0 = (size_t)bh * Nn + (size_t)c * CH;
    const int tid = threadIdx.x;
    const float gm = d_gmax;

    float* pk = d_phik + tok0 * Mm;
    #pragma unroll
    for (int rep = 0; rep < 16; rep++) {
        int idx = (rep*256 + tid) * 4;
        float4 t = *reinterpret_cast<const float4*>(pk + idx);
        t.x = __expf(t.x-gm)*INV_SQRT_M + EPS_PHI;
        t.y = __expf(t.y-gm)*INV_SQRT_M + EPS_PHI;
        t.z = __expf(t.z-gm)*INV_SQRT_M + EPS_PHI;
        t.w = __expf(t.w-gm)*INV_SQRT_M + EPS_PHI;
        *reinterpret_cast<float4*>(pk + idx)   = t;
        *reinterpret_cast<float4*>(phis + idx) = t;
    }
    #pragma unroll
    for (int rep = 0; rep < 8; rep++) {
        int idx = (rep*256 + tid) * 4;
        *reinterpret_cast<float4*>(vs + idx) =
            *reinterpret_cast<const float4*>(vg + tok0*Dd + idx);
    }
    __syncthreads();

    const int tx = tid & 15, ty = tid >> 4;
    const int m0 = ty*8, d0 = tx*4;
    u64 acc2[8][2];
    float zacc[8];
    #pragma unroll
    for (int u = 0; u < 8; u++) {
        zacc[u] = 0.f;
        acc2[u][0] = 0ull; acc2[u][1] = 0ull;
    }
    for (int i = 0; i < 128; i++) {
        float a[8];
        float4 t;
        t = *reinterpret_cast<const float4*>(&phis[i*128 + m0]);     a[0]=t.x;a[1]=t.y;a[2]=t.z;a[3]=t.w;
        t = *reinterpret_cast<const float4*>(&phis[i*128 + m0 + 4]); a[4]=t.x;a[5]=t.y;a[6]=t.z;a[7]=t.w;
        u64 a2[8];
        #pragma unroll
        for (int u = 0; u < 8; u++) a2[u] = pk2(a[u], a[u]);
        ulonglong2 bb = *reinterpret_cast<const ulonglong2*>(&vs[i*64 + d0]);
        #pragma unroll
        for (int u = 0; u < 8; u++) {
            acc2[u][0] = ffma2(a2[u], bb.x, acc2[u][0]);
            acc2[u][1] = ffma2(a2[u], bb.y, acc2[u][1]);
        }
        if (tx == 0) {
            #pragma unroll
            for (int u = 0; u < 8; u++) zacc[u] += a[u];
        }
    }
    float* Sg = d_S + (size_t)(bh*NC + c) * (Mm*Dd);
    #pragma unroll
    for (int u = 0; u < 8; u++) {
        float4 t;
        upk2(acc2[u][0], t.x, t.y);
        upk2(acc2[u][1], t.z, t.w);
        *reinterpret_cast<float4*>(Sg + (m0+u)*Dd + d0) = t;
    }
    if (tx == 0) {
        float* zg = d_zz + (bh*NC + c) * Mm;
        #pragma unroll
        for (int u = 0; u < 8; u++) zg[m0+u] = zacc[u];
    }
}

// ---------------------------------------------------------------------------
// K3: exclusive prefix over the 32 chunks (unchanged)
// ---------------------------------------------------------------------------
__global__ __launch_bounds__(256) void k_scan() {
    const int gid = blockIdx.x * 256 + threadIdx.x;
    if (blockIdx.x < 2048) {
        const int bh = gid >> 13;
        const int e  = gid & 8191;
        const size_t p = (size_t)bh * NC * (Mm*Dd) + e;
        float v[NC];
        #pragma unroll
        for (int c = 0; c < NC; c++) v[c] = d_S[p + (size_t)c * (Mm*Dd)];
        float acc = 0.f;
        #pragma unroll
        for (int c = 0; c < NC; c++) {
            d_S[p + (size_t)c * (Mm*Dd)] = acc;
            acc += v[c];
        }
    } else {
        const int idx = gid - 2048*256;
        const int bh = idx >> 7, m = idx & 127;
        const size_t p = (size_t)bh * NC * Mm + m;
        float v[NC];
        #pragma unroll
        for (int c = 0; c < NC; c++) v[c] = d_zz[p + c*Mm];
        float acc = 0.f;
        #pragma unroll
        for (int c = 0; c < NC; c++) {
            d_zz[p + c*Mm] = acc;
            acc += v[c];
        }
    }
}

// ---------------------------------------------------------------------------
// K4 (warp-MMA): R6 structure + paired-tile B loads (ldmatrix.x4).
// Causal loops use dynamic bounds (no unroll+break) to keep ptxas light.
// ---------------------------------------------------------------------------
#define OF_DEN 0
#define SQ_HI  1024
#define SQ_LO  (SQ_HI + 34816)
#define SK_HI  (SQ_LO + 34816)
#define SK_LO  (SK_HI + 34816)
#define SV_HI  (SK_LO + 34816)
#define SV_LO  (SV_HI + 19584)
#define SS_HI  (SV_LO + 19584)
#define SS_LO  (SS_HI + 19584)
#define SM4T   (SS_LO + 19584)   // 218624 bytes

__global__ __launch_bounds__(256) void k_out_mma(const float* __restrict__ vg,
                                                 float* __restrict__ outg) {
    extern __shared__ char smc[];
    const u32 sb = s2u(smc);
    float* den_s = (float*)(smc + OF_DEN);
    const int tid = threadIdx.x, wid = tid >> 5, lane = tid & 31;
    const int bid = blockIdx.x, bh = bid >> 5, c = bid & 31;
    const size_t tok0 = (size_t)bh * Nn + (size_t)c * CH;

    const float* pqg = d_phiq + tok0 * Mm;
    const float* pkg = d_phik + tok0 * Mm;
    #pragma unroll
    for (int it = 0; it < 16; it++) {
        int idx = (it*256 + tid) * 4;
        int r = idx >> 7, cc = idx & 127;
        u32 off = (u32)r * SR + (u32)cc * 2;
        float4 t = *reinterpret_cast<const float4*>(pqg + idx);
        u16 h0,l0,h1,l1,h2,l2,h3,l3;
        split2(t.x,h0,l0); split2(t.y,h1,l1); split2(t.z,h2,l2); split2(t.w,h3,l3);
        *(u32*)(smc+SQ_HI+off)   = (u32)h0 | ((u32)h1<<16);
        *(u32*)(smc+SQ_HI+off+4) = (u32)h2 | ((u32)h3<<16);
        *(u32*)(smc+SQ_LO+off)   = (u32)l0 | ((u32)l1<<16);
        *(u32*)(smc+SQ_LO+off+4) = (u32)l2 | ((u32)l3<<16);
        t = *reinterpret_cast<const float4*>(pkg + idx);
        split2(t.x,h0,l0); split2(t.y,h1,l1); split2(t.z,h2,l2); split2(t.w,h3,l3);
        *(u32*)(smc+SK_HI+off)   = (u32)h0 | ((u32)h1<<16);
        *(u32*)(smc+SK_HI+off+4) = (u32)h2 | ((u32)h3<<16);
        *(u32*)(smc+SK_LO+off)   = (u32)l0 | ((u32)l1<<16);
        *(u32*)(smc+SK_LO+off+4) = (u32)l2 | ((u32)l3<<16);
    }

    const float* Sg = d_S + (size_t)(bh*NC + c) * (Mm*Dd);
    #pragma unroll
    for (int it = 0; it < 4; it++) {
        int t4 = it*256 + tid;
        int jp = t4 >> 4, dg = (t4 & 15) << 2;
        float4 va = *reinterpret_cast<const float4*>(vg + (tok0 + 2*jp)*Dd + dg);
        float4 vb = *reinterpret_cast<const float4*>(vg + (tok0 + 2*jp + 1)*Dd + dg);
        float fa[4] = {va.x, va.y, va.z, va.w};
        float fb[4] = {vb.x, vb.y, vb.z, vb.w};
        #pragma unroll
        for (int e = 0; e < 4; e++) {
            u16 ha,la,hb,lb;
            split2(fa[e], ha, la); split2(fb[e], hb, lb);
            u32 off = (u32)(dg+e) * SR + (u32)jp * 4;
            *(u32*)(smc+SV_HI+off) = (u32)ha | ((u32)hb<<16);
            *(u32*)(smc+SV_LO+off) = (u32)la | ((u32)lb<<16);
        }
        va = *reinterpret_cast<const float4*>(Sg + (2*jp)*Dd + dg);
        vb = *reinterpret_cast<const float4*>(Sg + (2*jp + 1)*Dd + dg);
        float ga[4] = {va.x, va.y, va.z, va.w};
        float gb[4] = {vb.x, vb.y, vb.z, vb.w};
        #pragma unroll
        for (int e = 0; e < 4; e++) {
            u16 ha,la,hb,lb;
            split2(ga[e], ha, la); split2(gb[e], hb, lb);
            u32 off = (u32)(dg+e) * SR + (u32)jp * 4;
            *(u32*)(smc+SS_HI+off) = (u32)ha | ((u32)hb<<16);
            *(u32*)(smc+SS_LO+off) = (u32)la | ((u32)lb<<16);
        }
    }
    if (tid < 64) {
        int cp = tid * 2;
        u32 off = 64u * SR + (u32)tid * 4;
        *(u32*)(smc+SV_HI+off) = 0x3F803F80u;
        *(u32*)(smc+SV_LO+off) = 0u;
        const float* zg = d_zz + (bh*NC + c) * Mm;
        u16 h0,l0,h1,l1;
        split2(zg[cp],   h0, l0);
        split2(zg[cp+1], h1, l1);
        *(u32*)(smc+SS_HI+off) = (u32)h0 | ((u32)h1<<16);
        *(u32*)(smc+SS_LO+off) = (u32)l0 | ((u32)l1<<16);
    }
    for (int t4 = tid; t4 < 7*64; t4 += 256) {
        int r = 65 + t4/64;
        u32 off = (u32)r * SR + (u32)(t4 % 64) * 4;
        *(u32*)(smc+SV_HI+off) = 0u;
        *(u32*)(smc+SV_LO+off) = 0u;
        *(u32*)(smc+SS_HI+off) = 0u;
        *(u32*)(smc+SS_LO+off) = 0u;
    }
    __syncthreads();

    const int ib = (wid < 4) ? wid : (7 - (wid - 4));
    const int i0 = ib * 16;

    // ---- GEMM1: A = phiq . phik^T, causal tile pairs 0..ib (dynamic bound) ----
    float acc[16][4];
    #pragma unroll
    for (int nt = 0; nt < 16; nt++)
        #pragma unroll
        for (int e = 0; e < 4; e++) acc[nt][e] = 0.f;

    for (int kk = 0; kk < 8; kk++) {
        int k0 = kk * 16;
        u32 qh0,qh1,qh2,qh3, ql0,ql1,ql2,ql3;
        ldsm4(qh0,qh1,qh2,qh3, a_addr(sb+SQ_HI, i0, k0, lane));
        ldsm4(ql0,ql1,ql2,ql3, a_addr(sb+SQ_LO, i0, k0, lane));
        for (int np = 0; np <= ib; np++) {      // tile pair (2np, 2np+1)
            u32 bh0,bh1,bh2,bh3, bl0,bl1,bl2,bl3;
            ldsm4(bh0,bh1,bh2,bh3, b2_addr(sb+SK_HI, np*16, k0, lane));
            ldsm4(bl0,bl1,bl2,bl3, b2_addr(sb+SK_LO, np*16, k0, lane));
            mma16816(acc[2*np],   qh0,qh1,qh2,qh3, bh0,bh1);
            mma16816(acc[2*np],   qh0,qh1,qh2,qh3, bl0,bl1);
            mma16816(acc[2*np],   ql0,ql1,ql2,ql3, bh0,bh1);
            mma16816(acc[2*np+1], qh0,qh1,qh2,qh3, bh2,bh3);
            mma16816(acc[2*np+1], qh0,qh1,qh2,qh3, bl2,bl3);
            mma16816(acc[2*np+1], ql0,ql1,ql2,ql3, bh2,bh3);
        }
    }

    __syncthreads();

    {
        const int m1 = i0 + (lane >> 2);
        const int m2 = m1 + 8;
        const int ntmax1 = 2*ib + 1;
        for (int nt = 0; nt <= ntmax1; nt++) {   // dynamic bound, no unroll
            int jj = nt*8 + 2*(lane & 3);
            float a0 = (jj     <= m1) ? acc[nt][0] : 0.f;
            float a1 = (jj + 1 <= m1) ? acc[nt][1] : 0.f;
            float a2 = (jj     <= m2) ? acc[nt][2] : 0.f;
            float a3 = (jj + 1 <= m2) ? acc[nt][3] : 0.f;
            u16 h0,l0,h1,l1;
            split2(a0, h0, l0); split2(a1, h1, l1);
            u32 off = (u32)m1 * SR + (u32)jj * 2;
            *(u32*)(smc+SK_HI+off) = (u32)h0 | ((u32)h1<<16);
            *(u32*)(smc+SK_LO+off) = (u32)l0 | ((u32)l1<<16);
            split2(a2, h0, l0); split2(a3, h1, l1);
            off = (u32)m2 * SR + (u32)jj * 2;
            *(u32*)(smc+SK_HI+off) = (u32)h0 | ((u32)h1<<16);
            *(u32*)(smc+SK_LO+off) = (u32)l0 | ((u32)l1<<16);
        }
    }
    __syncwarp();

    // ---- GEMM2: D2 = A.VT + phiq.ST, tile pairs 0..3 + tile 8 ----
    float o[9][4];
    #pragma unroll
    for (int nt = 0; nt < 9; nt++)
        #pragma unroll
        for (int e = 0; e < 4; e++) o[nt][e] = 0.f;

    for (int kk = 0; kk < 8; kk++) {
        int k0 = kk * 16;
        u32 qh0,qh1,qh2,qh3, ql0,ql1,ql2,ql3;
        ldsm4(qh0,qh1,qh2,qh3, a_addr(sb+SQ_HI, i0, k0, lane));
        ldsm4(ql0,ql1,ql2,ql3, a_addr(sb+SQ_LO, i0, k0, lane));
        const bool doA = (kk <= ib);
        u32 ah0=0,ah1=0,ah2=0,ah3=0, al0=0,al1=0,al2=0,al3=0;
        if (doA) {
            ldsm4(ah0,ah1,ah2,ah3, a_addr(sb+SK_HI, i0, k0, lane));
            ldsm4(al0,al1,al2,al3, a_addr(sb+SK_LO, i0, k0, lane));
        }
        #pragma unroll
        for (int np = 0; np < 4; np++) {        // tile pair (2np, 2np+1)
            u32 sh0,sh1,sh2,sh3, sl0,sl1,sl2,sl3;
            ldsm4(sh0,sh1,sh2,sh3, b2_addr(sb+SS_HI, np*16, k0, lane));
            ldsm4(sl0,sl1,sl2,sl3, b2_addr(sb+SS_LO, np*16, k0, lane));
            mma16816(o[2*np],   qh0,qh1,qh2,qh3, sh0,sh1);
            mma16816(o[2*np],   qh0,qh1,qh2,qh3, sl0,sl1);
            mma16816(o[2*np],   ql0,ql1,ql2,ql3, sh0,sh1);
            mma16816(o[2*np+1], qh0,qh1,qh2,qh3, sh2,sh3);
            mma16816(o[2*np+1], qh0,qh1,qh2,qh3, sl2,sl3);
            mma16816(o[2*np+1], ql0,ql1,ql2,ql3, sh2,sh3);
            if (doA) {
                u32 vh0,vh1,vh2,vh3, vl0,vl1,vl2,vl3;
                ldsm4(vh0,vh1,vh2,vh3, b2_addr(sb+SV_HI, np*16, k0, lane));
                ldsm4(vl0,vl1,vl2,vl3, b2_addr(sb+SV_LO, np*16, k0, lane));
                mma16816(o[2*np],   ah0,ah1,ah2,ah3, vh0,vh1);
                mma16816(o[2*np],   ah0,ah1,ah2,ah3, vl0,vl1);
                mma16816(o[2*np],   al0,al1,al2,al3, vh0,vh1);
                mma16816(o[2*np+1], ah0,ah1,ah2,ah3, vh2,vh3);
                mma16816(o[2*np+1], ah0,ah1,ah2,ah3, vl2,vl3);
                mma16816(o[2*np+1], al0,al1,al2,al3, vh2,vh3);
            }
        }
        {   // tile 8 (den column)
            u32 sh0,sh1, sl0,sl1;
            ldsm2(sh0,sh1, b_addr(sb+SS_HI, 64, k0, lane));
            ldsm2(sl0,sl1, b_addr(sb+SS_LO, 64, k0, lane));
            mma16816(o[8], qh0,qh1,qh2,qh3, sh0,sh1);
            mma16816(o[8], qh0,qh1,qh2,qh3, sl0,sl1);
            mma16816(o[8], ql0,ql1,ql2,ql3, sh0,sh1);
            if (doA) {
                u32 vh0,vh1, vl0,vl1;
                ldsm2(vh0,vh1, b_addr(sb+SV_HI, 64, k0, lane));
                ldsm2(vl0,vl1, b_addr(sb+SV_LO, 64, k0, lane));
                mma16816(o[8], ah0,ah1,ah2,ah3, vh0,vh1);
                mma16816(o[8], ah0,ah1,ah2,ah3, vl0,vl1);
                mma16816(o[8], al0,al1,al2,al3, vh0,vh1);
            }
        }
    }

    if ((lane & 3) == 0) {
        den_s[i0 + (lane >> 2)]     = 1.f / (o[8][0] + EPS_DEN);
        den_s[i0 + 8 + (lane >> 2)] = 1.f / (o[8][2] + EPS_DEN);
    }
    __syncwarp();
    {
        const int m1 = i0 + (lane >> 2);
        const int m2 = m1 + 8;
        const float inv1 = den_s[m1];
        const float inv2 = den_s[m2];
        #pragma unroll
        for (int nt = 0; nt < 8; nt++) {
            int n = nt*8 + 2*(lane & 3);
            float2 t1 = { o[nt][0]*inv1, o[nt][1]*inv1 };
            float2 t2 = { o[nt][2]*inv2, o[nt][3]*inv2 };
            *reinterpret_cast<float2*>(outg + (tok0 + m1)*Dd + n) = t1;
            *reinterpret_cast<float2*>(outg + (tok0 + m2)*Dd + n) = t2;
        }
    }
}

// ---------------------------------------------------------------------------

extern "C" void kernel_launch(void* const* d_in, const int* in_sizes, int n_in,
                              void* d_out, int out_size) {
    const float* q  = (const float*)d_in[0];
    const float* k  = (const float*)d_in[1];
    const float* v  = (const float*)d_in[2];
    const float* om = (const float*)d_in[3];
    float* out = (float*)d_out;

    const int SM2 = 24576 * 4;   // 98304
    cudaFuncSetAttribute(k_proj_mma,  cudaFuncAttributeMaxDynamicSharedMemorySize, SM1T);
    cudaFuncSetAttribute(k_phik_sums, cudaFuncAttributeMaxDynamicSharedMemorySize, SM2);
    cudaFuncSetAttribute(k_out_mma,   cudaFuncAttributeMaxDynamicSharedMemorySize, SM4T);

    k_proj_mma<<<2*NBT, 256, SM1T>>>(q, k, om);
    k_gmax<<<1, 256>>>();
    k_phik_sums<<<NBT, 256, SM2>>>(v);
    k_scan<<<2048 + 32, 256>>>();
    k_out_mma<<<NBT, 256, SM4T>>>(v, out);
}

// round 12
// speedup vs baseline: 1.1858x; 1.1858x over previous
#include <cuda_runtime.h>
#include <cuda_bf16.h>
#include <cstdint>

#define SCALE       0.35355339059327373f   // 64^(-1/4)
#define INV_SQRT_M  0.08838834764831843f   // 1/sqrt(128)
#define EPS_PHI     1e-4f
#define EPS_DEN     1e-6f

#define BH    64        // B*H = 4*16
#define Nn    4096
#define Dd    64
#define Mm    128
#define CH    128       // chunk length
#define NC    32        // chunks per head
#define NTOK  (BH*Nn)   // 262144
#define NBT   (NTOK/CH) // 2048 token-chunks

typedef unsigned long long u64;
typedef unsigned int u32;
typedef unsigned short u16;

// ---------------- packed fp32x2 (K2) ----------------
__device__ __forceinline__ u64 pk2(float x, float y) {
    u64 r; asm("mov.b64 %0, {%1,%2};" : "=l"(r) : "f"(x), "f"(y)); return r;
}
__device__ __forceinline__ void upk2(u64 p, float& x, float& y) {
    asm("mov.b64 {%0,%1}, %2;" : "=f"(x), "=f"(y) : "l"(p));
}
__device__ __forceinline__ u64 ffma2(u64 a, u64 b, u64 c) {
    u64 d; asm("fma.rn.f32x2 %0, %1, %2, %3;" : "=l"(d) : "l"(a), "l"(b), "l"(c)); return d;
}

// ---------------- warp MMA helpers ----------------
__device__ __forceinline__ u32 s2u(const void* p) {
    u32 a; asm("{ .reg .u64 t; cvta.to.shared.u64 t, %1; cvt.u32.u64 %0, t; }"
               : "=r"(a) : "l"(p));
    return a;
}
__device__ __forceinline__ void ldsm4(u32& r0, u32& r1, u32& r2, u32& r3, u32 addr) {
    asm volatile("ldmatrix.sync.aligned.m8n8.x4.shared.b16 {%0,%1,%2,%3}, [%4];"
                 : "=r"(r0), "=r"(r1), "=r"(r2), "=r"(r3) : "r"(addr));
}
__device__ __forceinline__ void ldsm2(u32& r0, u32& r1, u32 addr) {
    asm volatile("ldmatrix.sync.aligned.m8n8.x2.shared.b16 {%0,%1}, [%2];"
                 : "=r"(r0), "=r"(r1) : "r"(addr));
}
__device__ __forceinline__ void mma16816(float* d, u32 a0, u32 a1, u32 a2, u32 a3,
                                         u32 b0, u32 b1) {
    asm volatile("mma.sync.aligned.m16n8k16.row.col.f32.bf16.bf16.f32 "
                 "{%0,%1,%2,%3}, {%4,%5,%6,%7}, {%8,%9}, {%0,%1,%2,%3};"
                 : "+f"(d[0]), "+f"(d[1]), "+f"(d[2]), "+f"(d[3])
                 : "r"(a0), "r"(a1), "r"(a2), "r"(a3), "r"(b0), "r"(b1));
}

// bf16 split
__device__ __forceinline__ u16 bf16h(float x) {
    u16 u; asm("cvt.rn.bf16.f32 %0, %1;" : "=h"(u) : "f"(x)); return u;
}
__device__ __forceinline__ float bf2f(u16 u) {
    float f; asm("cvt.f32.bf16 %0, %1;" : "=f"(f) : "h"(u)); return f;
}
__device__ __forceinline__ void split2(float x, u16& h, u16& l) {
    h = bf16h(x); l = bf16h(x - bf2f(h));
}

// Tile row strides (bytes): 136-half rows (K4), 72-half rows (K1)
#define SR  272
#define SR1 144
__device__ __forceinline__ u32 a_addr_s(u32 base, int m0, int k0, int lane, int srb) {
    int r  = m0 + (lane & 7) + ((lane >> 3) & 1) * 8;
    int kc = k0 + (lane >> 4) * 8;
    return base + r * srb + kc * 2;
}
__device__ __forceinline__ u32 b_addr_s(u32 base, int n0, int k0, int lane, int srb) {
    int r  = n0 + (lane & 7);
    int kc = k0 + ((lane >> 3) & 1) * 8;
    return base + r * srb + kc * 2;
}
__device__ __forceinline__ u32 a_addr(u32 base, int m0, int k0, int lane) {
    return a_addr_s(base, m0, k0, lane, SR);
}
__device__ __forceinline__ u32 b_addr(u32 base, int n0, int k0, int lane) {
    return b_addr_s(base, n0, k0, lane, SR);
}

// Scratch
__device__ float d_phiq[(size_t)NTOK*Mm];
__device__ float d_phik[(size_t)NTOK*Mm];   // lp, then phi_k after K2
__device__ float d_S[(size_t)BH*NC*Mm*Dd];
__device__ float d_zz[BH*NC*Mm];
__device__ float d_bmax[NBT];
__device__ float d_gmax;

// ---------------------------------------------------------------------------
// K1 (warp-MMA): proj[128,128] = (x*scale)[128,64] @ omega^T  (exact R6)
// ---------------------------------------------------------------------------
#define P_SSP 0
#define P_SS  8192
#define P_RED 8704
#define P_XH  9728
#define P_XL  (P_XH + 18432)
#define P_OH  (P_XL + 18432)
#define P_OL  (P_OH + 18432)
#define SM1T  (P_OL + 18432)   // 83456 B

__global__ __launch_bounds__(256) void k_proj_mma(const float* __restrict__ qg,
                                                  const float* __restrict__ kg,
                                                  const float* __restrict__ omg) {
    extern __shared__ char smc[];
    const u32 sb = s2u(smc);
    float* ssp = (float*)(smc + P_SSP);
    float* ss  = (float*)(smc + P_SS);
    float* red = (float*)(smc + P_RED);

    const int bid = blockIdx.x;
    const bool isq = bid < NBT;
    const int tb  = isq ? bid : bid - NBT;
    const float* xg = (isq ? qg : kg) + (size_t)tb * CH * Dd;
    const int tid = threadIdx.x, wid = tid >> 5, lane = tid & 31;

    #pragma unroll
    for (int it = 0; it < 8; it++) {
        int f4g = it*256 + tid;
        int r = f4g >> 4, p = f4g & 15, c4 = p * 4;
        u32 off = (u32)r * SR1 + (u32)c4 * 2;
        float4 t = *reinterpret_cast<const float4*>(xg + r*Dd + c4);
        t.x *= SCALE; t.y *= SCALE; t.z *= SCALE; t.w *= SCALE;
        ssp[f4g] = t.x*t.x + t.y*t.y + t.z*t.z + t.w*t.w;
        u16 h0,l0,h1,l1,h2,l2,h3,l3;
        split2(t.x,h0,l0); split2(t.y,h1,l1); split2(t.z,h2,l2); split2(t.w,h3,l3);
        *(u32*)(smc+P_XH+off)   = (u32)h0 | ((u32)h1<<16);
        *(u32*)(smc+P_XH+off+4) = (u32)h2 | ((u32)h3<<16);
        *(u32*)(smc+P_XL+off)   = (u32)l0 | ((u32)l1<<16);
        *(u32*)(smc+P_XL+off+4) = (u32)l2 | ((u32)l3<<16);
        float4 w = *reinterpret_cast<const float4*>(omg + (size_t)f4g * 4);
        split2(w.x,h0,l0); split2(w.y,h1,l1); split2(w.z,h2,l2); split2(w.w,h3,l3);
        *(u32*)(smc+P_OH+off)   = (u32)h0 | ((u32)h1<<16);
        *(u32*)(smc+P_OH+off+4) = (u32)h2 | ((u32)h3<<16);
        *(u32*)(smc+P_OL+off)   = (u32)l0 | ((u32)l1<<16);
        *(u32*)(smc+P_OL+off+4) = (u32)l2 | ((u32)l3<<16);
    }
    __syncthreads();
    if (tid < 128) {
        float s = 0.f;
        #pragma unroll
        for (int j = 0; j < 16; j++) s += ssp[tid*16 + j];
        ss[tid] = 0.5f * s;
    }
    __syncthreads();

    const int i0 = wid * 16;
    float acc[16][4];
    #pragma unroll
    for (int nt = 0; nt < 16; nt++)
        #pragma unroll
        for (int e = 0; e < 4; e++) acc[nt][e] = 0.f;

    #pragma unroll
    for (int kk = 0; kk < 4; kk++) {
        int k0 = kk * 16;
        u32 xh0,xh1,xh2,xh3, xl0,xl1,xl2,xl3;
        ldsm4(xh0,xh1,xh2,xh3, a_addr_s(sb+P_XH, i0, k0, lane, SR1));
        ldsm4(xl0,xl1,xl2,xl3, a_addr_s(sb+P_XL, i0, k0, lane, SR1));
        #pragma unroll
        for (int nt = 0; nt < 16; nt++) {
            u32 oh0,oh1, ol0,ol1;
            ldsm2(oh0,oh1, b_addr_s(sb+P_OH, nt*8, k0, lane, SR1));
            ldsm2(ol0,ol1, b_addr_s(sb+P_OL, nt*8, k0, lane, SR1));
            mma16816(acc[nt], xh0,xh1,xh2,xh3, oh0,oh1);
            mma16816(acc[nt], xh0,xh1,xh2,xh3, ol0,ol1);
            mma16816(acc[nt], xl0,xl1,xl2,xl3, oh0,oh1);
        }
    }

    const int m1 = i0 + (lane >> 2);
    const int m2 = m1 + 8;
    const size_t tok0 = (size_t)tb * CH;

    if (isq) {
        float rm1 = -3.0e38f, rm2 = -3.0e38f;
        #pragma unroll
        for (int nt = 0; nt < 16; nt++) {
            rm1 = fmaxf(rm1, fmaxf(acc[nt][0], acc[nt][1]));
            rm2 = fmaxf(rm2, fmaxf(acc[nt][2], acc[nt][3]));
        }
        rm1 = fmaxf(rm1, __shfl_xor_sync(0xFFFFFFFFu, rm1, 1));
        rm1 = fmaxf(rm1, __shfl_xor_sync(0xFFFFFFFFu, rm1, 2));
        rm2 = fmaxf(rm2, __shfl_xor_sync(0xFFFFFFFFu, rm2, 1));
        rm2 = fmaxf(rm2, __shfl_xor_sync(0xFFFFFFFFu, rm2, 2));
        float* og = d_phiq + tok0 * Mm;
        #pragma unroll
        for (int nt = 0; nt < 16; nt++) {
            int jj = nt*8 + 2*(lane & 3);
            float2 t1, t2;
            t1.x = __expf(acc[nt][0]-rm1)*INV_SQRT_M + EPS_PHI;
            t1.y = __expf(acc[nt][1]-rm1)*INV_SQRT_M + EPS_PHI;
            t2.x = __expf(acc[nt][2]-rm2)*INV_SQRT_M + EPS_PHI;
            t2.y = __expf(acc[nt][3]-rm2)*INV_SQRT_M + EPS_PHI;
            *reinterpret_cast<float2*>(og + (size_t)m1*Mm + jj) = t1;
            *reinterpret_cast<float2*>(og + (size_t)m2*Mm + jj) = t2;
        }
    } else {
        const float s1 = ss[m1], s2 = ss[m2];
        float bm = -3.0e38f;
        float* og = d_phik + tok0 * Mm;
        #pragma unroll
        for (int nt = 0; nt < 16; nt++) {
            int jj = nt*8 + 2*(lane & 3);
            float2 t1, t2;
            t1.x = acc[nt][0] - s1; t1.y = acc[nt][1] - s1;
            t2.x = acc[nt][2] - s2; t2.y = acc[nt][3] - s2;
            bm = fmaxf(bm, fmaxf(fmaxf(t1.x, t1.y), fmaxf(t2.x, t2.y)));
            *reinterpret_cast<float2*>(og + (size_t)m1*Mm + jj) = t1;
            *reinterpret_cast<float2*>(og + (size_t)m2*Mm + jj) = t2;
        }
        red[tid] = bm;
        __syncthreads();
        for (int s = 128; s > 0; s >>= 1) {
            if (tid < s) red[tid] = fmaxf(red[tid], red[tid+s]);
            __syncthreads();
        }
        if (tid == 0) d_bmax[tb] = red[0];
    }
}

__global__ __launch_bounds__(256) void k_gmax() {
    __shared__ float red[256];
    const int tid = threadIdx.x;
    float m = -3.0e38f;
    for (int i = tid; i < NBT; i += 256) m = fmaxf(m, d_bmax[i]);
    red[tid] = m;
    __syncthreads();
    for (int s = 128; s > 0; s >>= 1) {
        if (tid < s) red[tid] = fmaxf(red[tid], red[tid+s]);
        __syncthreads();
    }
    if (tid == 0) d_gmax = red[0];
}

// ---------------------------------------------------------------------------
// K2: phi_k = exp(lp-gmax)/sqrt(M)+eps (written back); chunk sums (exact R6)
// ---------------------------------------------------------------------------
__global__ __launch_bounds__(256) void k_phik_sums(const float* __restrict__ vg) {
    extern __shared__ float sm[];
    float* phis = sm;            // [128][128]
    float* vs   = sm + 128*128;  // [128][64]
    const int bid = blockIdx.x;
    const int bh = bid >> 5, c = bid & 31;
    const size_t tok0 = (size_t)bh * Nn + (size_t)c * CH;
    const int tid = threadIdx.x;
    const float gm = d_gmax;

    float* pk = d_phik + tok0 * Mm;
    #pragma unroll
    for (int rep = 0; rep < 16; rep++) {
        int idx = (rep*256 + tid) * 4;
        float4 t = *reinterpret_cast<const float4*>(pk + idx);
        t.x = __expf(t.x-gm)*INV_SQRT_M + EPS_PHI;
        t.y = __expf(t.y-gm)*INV_SQRT_M + EPS_PHI;
        t.z = __expf(t.z-gm)*INV_SQRT_M + EPS_PHI;
        t.w = __expf(t.w-gm)*INV_SQRT_M + EPS_PHI;
        *reinterpret_cast<float4*>(pk + idx)   = t;
        *reinterpret_cast<float4*>(phis + idx) = t;
    }
    #pragma unroll
    for (int rep = 0; rep < 8; rep++) {
        int idx = (rep*256 + tid) * 4;
        *reinterpret_cast<float4*>(vs + idx) =
            *reinterpret_cast<const float4*>(vg + tok0*Dd + idx);
    }
    __syncthreads();

    const int tx = tid & 15, ty = tid >> 4;
    const int m0 = ty*8, d0 = tx*4;
    u64 acc2[8][2];
    float zacc[8];
    #pragma unroll
    for (int u = 0; u < 8; u++) {
        zacc[u] = 0.f;
        acc2[u][0] = 0ull; acc2[u][1] = 0ull;
    }
    for (int i = 0; i < 128; i++) {
        float a[8];
        float4 t;
        t = *reinterpret_cast<const float4*>(&phis[i*128 + m0]);     a[0]=t.x;a[1]=t.y;a[2]=t.z;a[3]=t.w;
        t = *reinterpret_cast<const float4*>(&phis[i*128 + m0 + 4]); a[4]=t.x;a[5]=t.y;a[6]=t.z;a[7]=t.w;
        u64 a2[8];
        #pragma unroll
        for (int u = 0; u < 8; u++) a2[u] = pk2(a[u], a[u]);
        ulonglong2 bb = *reinterpret_cast<const ulonglong2*>(&vs[i*64 + d0]);
        #pragma unroll
        for (int u = 0; u < 8; u++) {
            acc2[u][0] = ffma2(a2[u], bb.x, acc2[u][0]);
            acc2[u][1] = ffma2(a2[u], bb.y, acc2[u][1]);
        }
        if (tx == 0) {
            #pragma unroll
            for (int u = 0; u < 8; u++) zacc[u] += a[u];
        }
    }
    float* Sg = d_S + (size_t)(bh*NC + c) * (Mm*Dd);
    #pragma unroll
    for (int u = 0; u < 8; u++) {
        float4 t;
        upk2(acc2[u][0], t.x, t.y);
        upk2(acc2[u][1], t.z, t.w);
        *reinterpret_cast<float4*>(Sg + (m0+u)*Dd + d0) = t;
    }
    if (tx == 0) {
        float* zg = d_zz + (bh*NC + c) * Mm;
        #pragma unroll
        for (int u = 0; u < 8; u++) zg[m0+u] = zacc[u];
    }
}

// ---------------------------------------------------------------------------
// K3: exclusive prefix over the 32 chunks (unchanged)
// ---------------------------------------------------------------------------
__global__ __launch_bounds__(256) void k_scan() {
    const int gid = blockIdx.x * 256 + threadIdx.x;
    if (blockIdx.x < 2048) {
        const int bh = gid >> 13;
        const int e  = gid & 8191;
        const size_t p = (size_t)bh * NC * (Mm*Dd) + e;
        float v[NC];
        #pragma unroll
        for (int c = 0; c < NC; c++) v[c] = d_S[p + (size_t)c * (Mm*Dd)];
        float acc = 0.f;
        #pragma unroll
        for (int c = 0; c < NC; c++) {
            d_S[p + (size_t)c * (Mm*Dd)] = acc;
            acc += v[c];
        }
    } else {
        const int idx = gid - 2048*256;
        const int bh = idx >> 7, m = idx & 127;
        const size_t p = (size_t)bh * NC * Mm + m;
        float v[NC];
        #pragma unroll
        for (int c = 0; c < NC; c++) v[c] = d_zz[p + c*Mm];
        float acc = 0.f;
        #pragma unroll
        for (int c = 0; c < NC; c++) {
            d_zz[p + c*Mm] = acc;
            acc += v[c];
        }
    }
}

// ---------------------------------------------------------------------------
// K4 (warp-MMA, 512 threads / 16 warps): warp pair (pid, pid+8) shares an
// i-block and splits along n. GEMM1: causal np pairs by parity. GEMM2: output
// tiles 0-3 (lower) / 4-7 + den tile 8 (upper). Same smem, 4 warps/SMSP.
// ---------------------------------------------------------------------------
#define OF_DEN 0
#define SQ_HI  1024
#define SQ_LO  (SQ_HI + 34816)
#define SK_HI  (SQ_LO + 34816)
#define SK_LO  (SK_HI + 34816)
#define SV_HI  (SK_LO + 34816)
#define SV_LO  (SV_HI + 19584)
#define SS_HI  (SV_LO + 19584)
#define SS_LO  (SS_HI + 19584)
#define SM4T   (SS_LO + 19584)   // 218624 bytes

__global__ __launch_bounds__(512) void k_out_mma(const float* __restrict__ vg,
                                                 float* __restrict__ outg) {
    extern __shared__ char smc[];
    const u32 sb = s2u(smc);
    float* den_s = (float*)(smc + OF_DEN);
    const int tid = threadIdx.x, wid = tid >> 5, lane = tid & 31;
    const int pid = wid & 7, half = wid >> 3;   // pair id + n-half
    const int bid = blockIdx.x, bh = bid >> 5, c = bid & 31;
    const size_t tok0 = (size_t)bh * Nn + (size_t)c * CH;

    // ---- stage phi_q, phi_k (bf16 hi/lo) ----
    const float* pqg = d_phiq + tok0 * Mm;
    const float* pkg = d_phik + tok0 * Mm;
    #pragma unroll
    for (int it = 0; it < 8; it++) {
        int idx = (it*512 + tid) * 4;
        int r = idx >> 7, cc = idx & 127;
        u32 off = (u32)r * SR + (u32)cc * 2;
        float4 t = *reinterpret_cast<const float4*>(pqg + idx);
        u16 h0,l0,h1,l1,h2,l2,h3,l3;
        split2(t.x,h0,l0); split2(t.y,h1,l1); split2(t.z,h2,l2); split2(t.w,h3,l3);
        *(u32*)(smc+SQ_HI+off)   = (u32)h0 | ((u32)h1<<16);
        *(u32*)(smc+SQ_HI+off+4) = (u32)h2 | ((u32)h3<<16);
        *(u32*)(smc+SQ_LO+off)   = (u32)l0 | ((u32)l1<<16);
        *(u32*)(smc+SQ_LO+off+4) = (u32)l2 | ((u32)l3<<16);
        t = *reinterpret_cast<const float4*>(pkg + idx);
        split2(t.x,h0,l0); split2(t.y,h1,l1); split2(t.z,h2,l2); split2(t.w,h3,l3);
        *(u32*)(smc+SK_HI+off)   = (u32)h0 | ((u32)h1<<16);
        *(u32*)(smc+SK_HI+off+4) = (u32)h2 | ((u32)h3<<16);
        *(u32*)(smc+SK_LO+off)   = (u32)l0 | ((u32)l1<<16);
        *(u32*)(smc+SK_LO+off+4) = (u32)l2 | ((u32)l3<<16);
    }

    // ---- stage VT [72][128] and ST [72][128] ----
    const float* Sg = d_S + (size_t)(bh*NC + c) * (Mm*Dd);
    #pragma unroll
    for (int it = 0; it < 2; it++) {
        int t4 = it*512 + tid;                 // 0..1023
        int jp = t4 >> 4, dg = (t4 & 15) << 2;
        float4 va = *reinterpret_cast<const float4*>(vg + (tok0 + 2*jp)*Dd + dg);
        float4 vb = *reinterpret_cast<const float4*>(vg + (tok0 + 2*jp + 1)*Dd + dg);
        float fa[4] = {va.x, va.y, va.z, va.w};
        float fb[4] = {vb.x, vb.y, vb.z, vb.w};
        #pragma unroll
        for (int e = 0; e < 4; e++) {
            u16 ha,la,hb,lb;
            split2(fa[e], ha, la); split2(fb[e], hb, lb);
            u32 off = (u32)(dg+e) * SR + (u32)jp * 4;
            *(u32*)(smc+SV_HI+off) = (u32)ha | ((u32)hb<<16);
            *(u32*)(smc+SV_LO+off) = (u32)la | ((u32)lb<<16);
        }
        va = *reinterpret_cast<const float4*>(Sg + (2*jp)*Dd + dg);
        vb = *reinterpret_cast<const float4*>(Sg + (2*jp + 1)*Dd + dg);
        float ga[4] = {va.x, va.y, va.z, va.w};
        float gb[4] = {vb.x, vb.y, vb.z, vb.w};
        #pragma unroll
        for (int e = 0; e < 4; e++) {
            u16 ha,la,hb,lb;
            split2(ga[e], ha, la); split2(gb[e], hb, lb);
            u32 off = (u32)(dg+e) * SR + (u32)jp * 4;
            *(u32*)(smc+SS_HI+off) = (u32)ha | ((u32)hb<<16);
            *(u32*)(smc+SS_LO+off) = (u32)la | ((u32)lb<<16);
        }
    }
    if (tid < 64) {
        int cp = tid * 2;
        u32 off = 64u * SR + (u32)tid * 4;
        *(u32*)(smc+SV_HI+off) = 0x3F803F80u;
        *(u32*)(smc+SV_LO+off) = 0u;
        const float* zg = d_zz + (bh*NC + c) * Mm;
        u16 h0,l0,h1,l1;
        split2(zg[cp],   h0, l0);
        split2(zg[cp+1], h1, l1);
        *(u32*)(smc+SS_HI+off) = (u32)h0 | ((u32)h1<<16);
        *(u32*)(smc+SS_LO+off) = (u32)l0 | ((u32)l1<<16);
    }
    for (int t4 = tid; t4 < 7*64; t4 += 512) {
        int r = 65 + t4/64;
        u32 off = (u32)r * SR + (u32)(t4 % 64) * 4;
        *(u32*)(smc+SV_HI+off) = 0u;
        *(u32*)(smc+SV_LO+off) = 0u;
        *(u32*)(smc+SS_HI+off) = 0u;
        *(u32*)(smc+SS_LO+off) = 0u;
    }
    __syncthreads();

    const int ib = (pid < 4) ? pid : (7 - (pid - 4));   // 0..7
    const int i0 = ib * 16;

    // ---- GEMM1: A = phiq . phik^T, own np = {2s+half} ∩ [0, ib] ----
    float acc[8][4];
    #pragma unroll
    for (int s = 0; s < 8; s++)
        #pragma unroll
        for (int e = 0; e < 4; e++) acc[s][e] = 0.f;

    for (int kk = 0; kk < 8; kk++) {
        int k0 = kk * 16;
        u32 qh0,qh1,qh2,qh3, ql0,ql1,ql2,ql3;
        ldsm4(qh0,qh1,qh2,qh3, a_addr(sb+SQ_HI, i0, k0, lane));
        ldsm4(ql0,ql1,ql2,ql3, a_addr(sb+SQ_LO, i0, k0, lane));
        #pragma unroll
        for (int s = 0; s < 4; s++) {
            int np = 2*s + half;
            if (np <= ib) {
                #pragma unroll
                for (int tt = 0; tt < 2; tt++) {
                    int nt = 2*np + tt;
                    u32 bh0,bh1, bl0,bl1;
                    ldsm2(bh0,bh1, b_addr(sb+SK_HI, nt*8, k0, lane));
                    ldsm2(bl0,bl1, b_addr(sb+SK_LO, nt*8, k0, lane));
                    mma16816(acc[2*s+tt], qh0,qh1,qh2,qh3, bh0,bh1);
                    mma16816(acc[2*s+tt], qh0,qh1,qh2,qh3, bl0,bl1);
                    mma16816(acc[2*s+tt], ql0,ql1,ql2,ql3, bh0,bh1);
                }
            }
        }
    }

    __syncthreads();   // all warps done reading phik tiles

    // ---- mask causal, split, overwrite phik tiles (own columns only) ----
    {
        const int m1 = i0 + (lane >> 2);
        const int m2 = m1 + 8;
        #pragma unroll
        for (int s = 0; s < 4; s++) {
            int np = 2*s + half;
            if (np <= ib) {
                #pragma unroll
                for (int tt = 0; tt < 2; tt++) {
                    int nt = 2*np + tt;
                    int jj = nt*8 + 2*(lane & 3);
                    float a0 = (jj     <= m1) ? acc[2*s+tt][0] : 0.f;
                    float a1 = (jj + 1 <= m1) ? acc[2*s+tt][1] : 0.f;
                    float a2 = (jj     <= m2) ? acc[2*s+tt][2] : 0.f;
                    float a3 = (jj + 1 <= m2) ? acc[2*s+tt][3] : 0.f;
                    u16 h0,l0,h1,l1;
                    split2(a0, h0, l0); split2(a1, h1, l1);
                    u32 off = (u32)m1 * SR + (u32)jj * 2;
                    *(u32*)(smc+SK_HI+off) = (u32)h0 | ((u32)h1<<16);
                    *(u32*)(smc+SK_LO+off) = (u32)l0 | ((u32)l1<<16);
                    split2(a2, h0, l0); split2(a3, h1, l1);
                    off = (u32)m2 * SR + (u32)jj * 2;
                    *(u32*)(smc+SK_HI+off) = (u32)h0 | ((u32)h1<<16);
                    *(u32*)(smc+SK_LO+off) = (u32)l0 | ((u32)l1<<16);
                }
            }
        }
    }
    __syncthreads();   // A rows written by both warps of each pair

    // ---- GEMM2: D2 = A.VT + phiq.ST, tiles ntbase..ntbase+3 (+8 upper) ----
    float o[5][4];
    #pragma unroll
    for (int s = 0; s < 5; s++)
        #pragma unroll
        for (int e = 0; e < 4; e++) o[s][e] = 0.f;
    const int ntbase = half * 4;

    for (int kk = 0; kk < 8; kk++) {
        int k0 = kk * 16;
        u32 qh0,qh1,qh2,qh3, ql0,ql1,ql2,ql3;
        ldsm4(qh0,qh1,qh2,qh3, a_addr(sb+SQ_HI, i0, k0, lane));
        ldsm4(ql0,ql1,ql2,ql3, a_addr(sb+SQ_LO, i0, k0, lane));
        const bool doA = (kk <= ib);
        u32 ah0=0,ah1=0,ah2=0,ah3=0, al0=0,al1=0,al2=0,al3=0;
        if (doA) {
            ldsm4(ah0,ah1,ah2,ah3, a_addr(sb+SK_HI, i0, k0, lane));
            ldsm4(al0,al1,al2,al3, a_addr(sb+SK_LO, i0, k0, lane));
        }
        #pragma unroll
        for (int t = 0; t < 4; t++) {
            int nt = ntbase + t;
            u32 sh0,sh1, sl0,sl1;
            ldsm2(sh0,sh1, b_addr(sb+SS_HI, nt*8, k0, lane));
            ldsm2(sl0,sl1, b_addr(sb+SS_LO, nt*8, k0, lane));
            mma16816(o[t], qh0,qh1,qh2,qh3, sh0,sh1);
            mma16816(o[t], qh0,qh1,qh2,qh3, sl0,sl1);
            mma16816(o[t], ql0,ql1,ql2,ql3, sh0,sh1);
            if (doA) {
                u32 vh0,vh1, vl0,vl1;
                ldsm2(vh0,vh1, b_addr(sb+SV_HI, nt*8, k0, lane));
                ldsm2(vl0,vl1, b_addr(sb+SV_LO, nt*8, k0, lane));
                mma16816(o[t], ah0,ah1,ah2,ah3, vh0,vh1);
                mma16816(o[t], ah0,ah1,ah2,ah3, vl0,vl1);
                mma16816(o[t], al0,al1,al2,al3, vh0,vh1);
            }
        }
        if (half == 1) {   // tile 8 (den column) — warp-uniform branch
            u32 sh0,sh1, sl0,sl1;
            ldsm2(sh0,sh1, b_addr(sb+SS_HI, 64, k0, lane));
            ldsm2(sl0,sl1, b_addr(sb+SS_LO, 64, k0, lane));
            mma16816(o[4], qh0,qh1,qh2,qh3, sh0,sh1);
            mma16816(o[4], qh0,qh1,qh2,qh3, sl0,sl1);
            mma16816(o[4], ql0,ql1,ql2,ql3, sh0,sh1);
            if (doA) {
                u32 vh0,vh1, vl0,vl1;
                ldsm2(vh0,vh1, b_addr(sb+SV_HI, 64, k0, lane));
                ldsm2(vl0,vl1, b_addr(sb+SV_LO, 64, k0, lane));
                mma16816(o[4], ah0,ah1,ah2,ah3, vh0,vh1);
                mma16816(o[4], ah0,ah1,ah2,ah3, vl0,vl1);
                mma16816(o[4], al0,al1,al2,al3, vh0,vh1);
            }
        }
    }

    if (half == 1 && (lane & 3) == 0) {
        den_s[i0 + (lane >> 2)]     = 1.f / (o[4][0] + EPS_DEN);
        den_s[i0 + 8 + (lane >> 2)] = 1.f / (o[4][2] + EPS_DEN);
    }
    __syncthreads();   // den_s from upper warps -> all warps
    {
        const int m1 = i0 + (lane >> 2);
        const int m2 = m1 + 8;
        const float inv1 = den_s[m1];
        const float inv2 = den_s[m2];
        #pragma unroll
        for (int t = 0; t < 4; t++) {
            int n = (ntbase + t)*8 + 2*(lane & 3);
            float2 t1 = { o[t][0]*inv1, o[t][1]*inv1 };
            float2 t2 = { o[t][2]*inv2, o[t][3]*inv2 };
            *reinterpret_cast<float2*>(outg + (tok0 + m1)*Dd + n) = t1;
            *reinterpret_cast<float2*>(outg + (tok0 + m2)*Dd + n) = t2;
        }
    }
}

// ---------------------------------------------------------------------------

extern "C" void kernel_launch(void* const* d_in, const int* in_sizes, int n_in,
                              void* d_out, int out_size) {
    const float* q  = (const float*)d_in[0];
    const float* k  = (const float*)d_in[1];
    const float* v  = (const float*)d_in[2];
    const float* om = (const float*)d_in[3];
    float* out = (float*)d_out;

    const int SM2 = 24576 * 4;   // 98304
    cudaFuncSetAttribute(k_proj_mma,  cudaFuncAttributeMaxDynamicSharedMemorySize, SM1T);
    cudaFuncSetAttribute(k_phik_sums, cudaFuncAttributeMaxDynamicSharedMemorySize, SM2);
    cudaFuncSetAttribute(k_out_mma,   cudaFuncAttributeMaxDynamicSharedMemorySize, SM4T);

    k_proj_mma<<<2*NBT, 256, SM1T>>>(q, k, om);
    k_gmax<<<1, 256>>>();
    k_phik_sums<<<NBT, 256, SM2>>>(v);
    k_scan<<<2048 + 32, 256>>>();
    k_out_mma<<<NBT, 512, SM4T>>>(v, out);
}

// round 13
// speedup vs baseline: 1.2722x; 1.0729x over previous
#include <cuda_runtime.h>
#include <cuda_bf16.h>
#include <cstdint>

#define SCALE       0.35355339059327373f   // 64^(-1/4)
#define INV_SQRT_M  0.08838834764831843f   // 1/sqrt(128)
#define EPS_PHI     1e-4f
#define EPS_DEN     1e-6f

#define BH    64        // B*H = 4*16
#define Nn    4096
#define Dd    64
#define Mm    128
#define CH    128       // chunk length
#define NC    32        // chunks per head
#define NTOK  (BH*Nn)   // 262144
#define NBT   (NTOK/CH) // 2048 token-chunks

typedef unsigned long long u64;
typedef unsigned int u32;
typedef unsigned short u16;

// ---------------- warp MMA helpers ----------------
__device__ __forceinline__ u32 s2u(const void* p) {
    u32 a; asm("{ .reg .u64 t; cvta.to.shared.u64 t, %1; cvt.u32.u64 %0, t; }"
               : "=r"(a) : "l"(p));
    return a;
}
__device__ __forceinline__ void ldsm4(u32& r0, u32& r1, u32& r2, u32& r3, u32 addr) {
    asm volatile("ldmatrix.sync.aligned.m8n8.x4.shared.b16 {%0,%1,%2,%3}, [%4];"
                 : "=r"(r0), "=r"(r1), "=r"(r2), "=r"(r3) : "r"(addr));
}
__device__ __forceinline__ void ldsm2(u32& r0, u32& r1, u32 addr) {
    asm volatile("ldmatrix.sync.aligned.m8n8.x2.shared.b16 {%0,%1}, [%2];"
                 : "=r"(r0), "=r"(r1) : "r"(addr));
}
__device__ __forceinline__ void ldsm2t(u32& r0, u32& r1, u32 addr) {
    asm volatile("ldmatrix.sync.aligned.m8n8.x2.trans.shared.b16 {%0,%1}, [%2];"
                 : "=r"(r0), "=r"(r1) : "r"(addr));
}
__device__ __forceinline__ void mma16816(float* d, u32 a0, u32 a1, u32 a2, u32 a3,
                                         u32 b0, u32 b1) {
    asm volatile("mma.sync.aligned.m16n8k16.row.col.f32.bf16.bf16.f32 "
                 "{%0,%1,%2,%3}, {%4,%5,%6,%7}, {%8,%9}, {%0,%1,%2,%3};"
                 : "+f"(d[0]), "+f"(d[1]), "+f"(d[2]), "+f"(d[3])
                 : "r"(a0), "r"(a1), "r"(a2), "r"(a3), "r"(b0), "r"(b1));
}

// bf16 split
__device__ __forceinline__ u16 bf16h(float x) {
    u16 u; asm("cvt.rn.bf16.f32 %0, %1;" : "=h"(u) : "f"(x)); return u;
}
__device__ __forceinline__ float bf2f(u16 u) {
    float f; asm("cvt.f32.bf16 %0, %1;" : "=f"(f) : "h"(u)); return f;
}
__device__ __forceinline__ void split2(float x, u16& h, u16& l) {
    h = bf16h(x); l = bf16h(x - bf2f(h));
}

// Tile row strides (bytes): 136-half rows (K2/K4), 72-half rows (K1)
#define SR  272
#define SR1 144
__device__ __forceinline__ u32 a_addr_s(u32 base, int m0, int k0, int lane, int srb) {
    int r  = m0 + (lane & 7) + ((lane >> 3) & 1) * 8;
    int kc = k0 + (lane >> 4) * 8;
    return base + r * srb + kc * 2;
}
__device__ __forceinline__ u32 b_addr_s(u32 base, int n0, int k0, int lane, int srb) {
    int r  = n0 + (lane & 7);
    int kc = k0 + ((lane >> 3) & 1) * 8;
    return base + r * srb + kc * 2;
}
__device__ __forceinline__ u32 a_addr(u32 base, int m0, int k0, int lane) {
    return a_addr_s(base, m0, k0, lane, SR);
}
__device__ __forceinline__ u32 b_addr(u32 base, int n0, int k0, int lane) {
    return b_addr_s(base, n0, k0, lane, SR);
}
// trans-B address: storage [k][n] row-major; octet g in {0,1} -> stored rows
// k0+8g+l8 at byte col n0*2. Delivers B fragments [n][k] after HW transpose.
__device__ __forceinline__ u32 bt_addr(u32 base, int n0, int k0, int lane) {
    int l8 = lane & 7, g = (lane >> 3) & 1;
    return base + (u32)(k0 + g*8 + l8) * SR + (u32)n0 * 2;
}

// Scratch
__device__ float d_phiq[(size_t)NTOK*Mm];
__device__ float d_phik[(size_t)NTOK*Mm];   // lp, then phi_k after K2
__device__ float d_S[(size_t)BH*NC*Mm*Dd];  // S^T layout: [chunk][d=64][m=128]
__device__ float d_zz[BH*NC*Mm];
__device__ float d_bmax[NBT];
__device__ float d_gmax;

// ---------------------------------------------------------------------------
// K1 (warp-MMA): proj[128,128] = (x*scale)[128,64] @ omega^T  (exact R6/R12)
// ---------------------------------------------------------------------------
#define P_SSP 0
#define P_SS  8192
#define P_RED 8704
#define P_XH  9728
#define P_XL  (P_XH + 18432)
#define P_OH  (P_XL + 18432)
#define P_OL  (P_OH + 18432)
#define SM1T  (P_OL + 18432)   // 83456 B

__global__ __launch_bounds__(256) void k_proj_mma(const float* __restrict__ qg,
                                                  const float* __restrict__ kg,
                                                  const float* __restrict__ omg) {
    extern __shared__ char smc[];
    const u32 sb = s2u(smc);
    float* ssp = (float*)(smc + P_SSP);
    float* ss  = (float*)(smc + P_SS);
    float* red = (float*)(smc + P_RED);

    const int bid = blockIdx.x;
    const bool isq = bid < NBT;
    const int tb  = isq ? bid : bid - NBT;
    const float* xg = (isq ? qg : kg) + (size_t)tb * CH * Dd;
    const int tid = threadIdx.x, wid = tid >> 5, lane = tid & 31;

    #pragma unroll
    for (int it = 0; it < 8; it++) {
        int f4g = it*256 + tid;
        int r = f4g >> 4, p = f4g & 15, c4 = p * 4;
        u32 off = (u32)r * SR1 + (u32)c4 * 2;
        float4 t = *reinterpret_cast<const float4*>(xg + r*Dd + c4);
        t.x *= SCALE; t.y *= SCALE; t.z *= SCALE; t.w *= SCALE;
        ssp[f4g] = t.x*t.x + t.y*t.y + t.z*t.z + t.w*t.w;
        u16 h0,l0,h1,l1,h2,l2,h3,l3;
        split2(t.x,h0,l0); split2(t.y,h1,l1); split2(t.z,h2,l2); split2(t.w,h3,l3);
        *(u32*)(smc+P_XH+off)   = (u32)h0 | ((u32)h1<<16);
        *(u32*)(smc+P_XH+off+4) = (u32)h2 | ((u32)h3<<16);
        *(u32*)(smc+P_XL+off)   = (u32)l0 | ((u32)l1<<16);
        *(u32*)(smc+P_XL+off+4) = (u32)l2 | ((u32)l3<<16);
        float4 w = *reinterpret_cast<const float4*>(omg + (size_t)f4g * 4);
        split2(w.x,h0,l0); split2(w.y,h1,l1); split2(w.z,h2,l2); split2(w.w,h3,l3);
        *(u32*)(smc+P_OH+off)   = (u32)h0 | ((u32)h1<<16);
        *(u32*)(smc+P_OH+off+4) = (u32)h2 | ((u32)h3<<16);
        *(u32*)(smc+P_OL+off)   = (u32)l0 | ((u32)l1<<16);
        *(u32*)(smc+P_OL+off+4) = (u32)l2 | ((u32)l3<<16);
    }
    __syncthreads();
    if (tid < 128) {
        float s = 0.f;
        #pragma unroll
        for (int j = 0; j < 16; j++) s += ssp[tid*16 + j];
        ss[tid] = 0.5f * s;
    }
    __syncthreads();

    const int i0 = wid * 16;
    float acc[16][4];
    #pragma unroll
    for (int nt = 0; nt < 16; nt++)
        #pragma unroll
        for (int e = 0; e < 4; e++) acc[nt][e] = 0.f;

    #pragma unroll
    for (int kk = 0; kk < 4; kk++) {
        int k0 = kk * 16;
        u32 xh0,xh1,xh2,xh3, xl0,xl1,xl2,xl3;
        ldsm4(xh0,xh1,xh2,xh3, a_addr_s(sb+P_XH, i0, k0, lane, SR1));
        ldsm4(xl0,xl1,xl2,xl3, a_addr_s(sb+P_XL, i0, k0, lane, SR1));
        #pragma unroll
        for (int nt = 0; nt < 16; nt++) {
            u32 oh0,oh1, ol0,ol1;
            ldsm2(oh0,oh1, b_addr_s(sb+P_OH, nt*8, k0, lane, SR1));
            ldsm2(ol0,ol1, b_addr_s(sb+P_OL, nt*8, k0, lane, SR1));
            mma16816(acc[nt], xh0,xh1,xh2,xh3, oh0,oh1);
            mma16816(acc[nt], xh0,xh1,xh2,xh3, ol0,ol1);
            mma16816(acc[nt], xl0,xl1,xl2,xl3, oh0,oh1);
        }
    }

    const int m1 = i0 + (lane >> 2);
    const int m2 = m1 + 8;
    const size_t tok0 = (size_t)tb * CH;

    if (isq) {
        float rm1 = -3.0e38f, rm2 = -3.0e38f;
        #pragma unroll
        for (int nt = 0; nt < 16; nt++) {
            rm1 = fmaxf(rm1, fmaxf(acc[nt][0], acc[nt][1]));
            rm2 = fmaxf(rm2, fmaxf(acc[nt][2], acc[nt][3]));
        }
        rm1 = fmaxf(rm1, __shfl_xor_sync(0xFFFFFFFFu, rm1, 1));
        rm1 = fmaxf(rm1, __shfl_xor_sync(0xFFFFFFFFu, rm1, 2));
        rm2 = fmaxf(rm2, __shfl_xor_sync(0xFFFFFFFFu, rm2, 1));
        rm2 = fmaxf(rm2, __shfl_xor_sync(0xFFFFFFFFu, rm2, 2));
        float* og = d_phiq + tok0 * Mm;
        #pragma unroll
        for (int nt = 0; nt < 16; nt++) {
            int jj = nt*8 + 2*(lane & 3);
            float2 t1, t2;
            t1.x = __expf(acc[nt][0]-rm1)*INV_SQRT_M + EPS_PHI;
            t1.y = __expf(acc[nt][1]-rm1)*INV_SQRT_M + EPS_PHI;
            t2.x = __expf(acc[nt][2]-rm2)*INV_SQRT_M + EPS_PHI;
            t2.y = __expf(acc[nt][3]-rm2)*INV_SQRT_M + EPS_PHI;
            *reinterpret_cast<float2*>(og + (size_t)m1*Mm + jj) = t1;
            *reinterpret_cast<float2*>(og + (size_t)m2*Mm + jj) = t2;
        }
    } else {
        const float s1 = ss[m1], s2 = ss[m2];
        float bm = -3.0e38f;
        float* og = d_phik + tok0 * Mm;
        #pragma unroll
        for (int nt = 0; nt < 16; nt++) {
            int jj = nt*8 + 2*(lane & 3);
            float2 t1, t2;
            t1.x = acc[nt][0] - s1; t1.y = acc[nt][1] - s1;
            t2.x = acc[nt][2] - s2; t2.y = acc[nt][3] - s2;
            bm = fmaxf(bm, fmaxf(fmaxf(t1.x, t1.y), fmaxf(t2.x, t2.y)));
            *reinterpret_cast<float2*>(og + (size_t)m1*Mm + jj) = t1;
            *reinterpret_cast<float2*>(og + (size_t)m2*Mm + jj) = t2;
        }
        red[tid] = bm;
        __syncthreads();
        for (int s = 128; s > 0; s >>= 1) {
            if (tid < s) red[tid] = fmaxf(red[tid], red[tid+s]);
            __syncthreads();
        }
        if (tid == 0) d_bmax[tb] = red[0];
    }
}

__global__ __launch_bounds__(256) void k_gmax() {
    __shared__ float red[256];
    const int tid = threadIdx.x;
    float m = -3.0e38f;
    for (int i = tid; i < NBT; i += 256) m = fmaxf(m, d_bmax[i]);
    red[tid] = m;
    __syncthreads();
    for (int s = 128; s > 0; s >>= 1) {
        if (tid < s) red[tid] = fmaxf(red[tid], red[tid+s]);
        __syncthreads();
    }
    if (tid == 0) d_gmax = red[0];
}

// ---------------------------------------------------------------------------
// K2 (warp-MMA): S^T[d,m] = sum_i V[i,d] * phik[i,m].
//   A = V^T [64][128]  (transposed staging, proven K4 pattern)
//   B = phik [i][m] row-major, read via ldmatrix.trans
// z[m] = colsum phik via smem reduction. phik written back to gmem (as R12).
// Warp w: d-tile = w>>1 (16 d rows), m-half = w&1 (8 B tiles).
// ---------------------------------------------------------------------------
#define Q_PKH 0
#define Q_PKL (Q_PKH + 34816)
#define Q_VTH (Q_PKL + 34816)
#define Q_VTL (Q_VTH + 17408)
#define Q_ZP  (Q_VTL + 17408)
#define SM2T  (Q_ZP + 1024)   // 105472 B

__global__ __launch_bounds__(256) void k_sums_mma(const float* __restrict__ vg) {
    extern __shared__ char smc[];
    const u32 sb = s2u(smc);
    float* zp = (float*)(smc + Q_ZP);
    const int tid = threadIdx.x, wid = tid >> 5, lane = tid & 31;
    const int bid = blockIdx.x, bh = bid >> 5, c = bid & 31;
    const size_t tok0 = (size_t)bh * Nn + (size_t)c * CH;
    const float gm = d_gmax;

    // ---- stage phik: exp + writeback + split into [i][m] tiles ----
    float* pk = d_phik + tok0 * Mm;
    #pragma unroll
    for (int it = 0; it < 16; it++) {
        int idx = (it*256 + tid) * 4;
        int i = idx >> 7, m = idx & 127;
        u32 off = (u32)i * SR + (u32)m * 2;
        float4 t = *reinterpret_cast<const float4*>(pk + idx);
        t.x = __expf(t.x-gm)*INV_SQRT_M + EPS_PHI;
        t.y = __expf(t.y-gm)*INV_SQRT_M + EPS_PHI;
        t.z = __expf(t.z-gm)*INV_SQRT_M + EPS_PHI;
        t.w = __expf(t.w-gm)*INV_SQRT_M + EPS_PHI;
        *reinterpret_cast<float4*>(pk + idx) = t;
        u16 h0,l0,h1,l1,h2,l2,h3,l3;
        split2(t.x,h0,l0); split2(t.y,h1,l1); split2(t.z,h2,l2); split2(t.w,h3,l3);
        *(u32*)(smc+Q_PKH+off)   = (u32)h0 | ((u32)h1<<16);
        *(u32*)(smc+Q_PKH+off+4) = (u32)h2 | ((u32)h3<<16);
        *(u32*)(smc+Q_PKL+off)   = (u32)l0 | ((u32)l1<<16);
        *(u32*)(smc+Q_PKL+off+4) = (u32)l2 | ((u32)l3<<16);
    }

    // ---- stage V^T [64][128] (transposed gather, split) ----
    #pragma unroll
    for (int it = 0; it < 4; it++) {
        int t4 = it*256 + tid;                 // 0..1023
        int jp = t4 >> 4, dg = (t4 & 15) << 2; // token pair, d-group
        float4 va = *reinterpret_cast<const float4*>(vg + (tok0 + 2*jp)*Dd + dg);
        float4 vb = *reinterpret_cast<const float4*>(vg + (tok0 + 2*jp + 1)*Dd + dg);
        float fa[4] = {va.x, va.y, va.z, va.w};
        float fb[4] = {vb.x, vb.y, vb.z, vb.w};
        #pragma unroll
        for (int e = 0; e < 4; e++) {
            u16 ha,la,hb,lb;
            split2(fa[e], ha, la); split2(fb[e], hb, lb);
            u32 off = (u32)(dg+e) * SR + (u32)jp * 4;
            *(u32*)(smc+Q_VTH+off) = (u32)ha | ((u32)hb<<16);
            *(u32*)(smc+Q_VTL+off) = (u32)la | ((u32)lb<<16);
        }
    }
    __syncthreads();

    // ---- z partials: thread t sums column m=t&127 over half the i rows ----
    {
        int m = tid & 127, ih = tid >> 7;
        float s = 0.f;
        int ibase = ih * 64;
        #pragma unroll 8
        for (int i = 0; i < 64; i++) {
            u32 off = (u32)(ibase + i) * SR + (u32)m * 2;
            u16 h = *(u16*)(smc+Q_PKH+off);
            u16 l = *(u16*)(smc+Q_PKL+off);
            s += bf2f(h) + bf2f(l);
        }
        zp[tid] = s;
    }
    __syncthreads();
    if (tid < 128) d_zz[(bh*NC + c)*Mm + tid] = zp[tid] + zp[tid + 128];

    // ---- GEMM: S^T = V^T . phik ----
    const int dt = wid >> 1, mh = wid & 1;
    const int d0 = dt * 16;
    float acc[8][4];
    #pragma unroll
    for (int t = 0; t < 8; t++)
        #pragma unroll
        for (int e = 0; e < 4; e++) acc[t][e] = 0.f;

    for (int kk = 0; kk < 8; kk++) {
        int k0 = kk * 16;
        u32 ah0,ah1,ah2,ah3, al0,al1,al2,al3;
        ldsm4(ah0,ah1,ah2,ah3, a_addr(sb+Q_VTH, d0, k0, lane));
        ldsm4(al0,al1,al2,al3, a_addr(sb+Q_VTL, d0, k0, lane));
        #pragma unroll
        for (int t = 0; t < 8; t++) {
            int n0 = (mh*8 + t) * 8;
            u32 bh0,bh1, bl0,bl1;
            ldsm2t(bh0,bh1, bt_addr(sb+Q_PKH, n0, k0, lane));
            ldsm2t(bl0,bl1, bt_addr(sb+Q_PKL, n0, k0, lane));
            mma16816(acc[t], ah0,ah1,ah2,ah3, bh0,bh1);
            mma16816(acc[t], ah0,ah1,ah2,ah3, bl0,bl1);
            mma16816(acc[t], al0,al1,al2,al3, bh0,bh1);
        }
    }

    // ---- write S^T [64][128] ----
    float* SgT = d_S + (size_t)(bh*NC + c) * (Mm*Dd);
    const int d1 = d0 + (lane >> 2), d2 = d1 + 8;
    #pragma unroll
    for (int t = 0; t < 8; t++) {
        int m = (mh*8 + t)*8 + 2*(lane & 3);
        float2 t1 = { acc[t][0], acc[t][1] };
        float2 t2 = { acc[t][2], acc[t][3] };
        *reinterpret_cast<float2*>(SgT + d1*Mm + m) = t1;
        *reinterpret_cast<float2*>(SgT + d2*Mm + m) = t2;
    }
}

// ---------------------------------------------------------------------------
// K3: exclusive prefix over the 32 chunks (element-wise -> layout-agnostic)
// ---------------------------------------------------------------------------
__global__ __launch_bounds__(256) void k_scan() {
    const int gid = blockIdx.x * 256 + threadIdx.x;
    if (blockIdx.x < 2048) {
        const int bh = gid >> 13;
        const int e  = gid & 8191;
        const size_t p = (size_t)bh * NC * (Mm*Dd) + e;
        float v[NC];
        #pragma unroll
        for (int c = 0; c < NC; c++) v[c] = d_S[p + (size_t)c * (Mm*Dd)];
        float acc = 0.f;
        #pragma unroll
        for (int c = 0; c < NC; c++) {
            d_S[p + (size_t)c * (Mm*Dd)] = acc;
            acc += v[c];
        }
    } else {
        const int idx = gid - 2048*256;
        const int bh = idx >> 7, m = idx & 127;
        const size_t p = (size_t)bh * NC * Mm + m;
        float v[NC];
        #pragma unroll
        for (int c = 0; c < NC; c++) v[c] = d_zz[p + c*Mm];
        float acc = 0.f;
        #pragma unroll
        for (int c = 0; c < NC; c++) {
            d_zz[p + c*Mm] = acc;
            acc += v[c];
        }
    }
}

// ---------------------------------------------------------------------------
// K4 (warp-MMA, 512 threads): exact R12 except ST staged directly from the
// new S^T gmem layout (coalesced split, no transpose gather).
// ---------------------------------------------------------------------------
#define OF_DEN 0
#define SQ_HI  1024
#define SQ_LO  (SQ_HI + 34816)
#define SK_HI  (SQ_LO + 34816)
#define SK_LO  (SK_HI + 34816)
#define SV_HI  (SK_LO + 34816)
#define SV_LO  (SV_HI + 19584)
#define SS_HI  (SV_LO + 19584)
#define SS_LO  (SS_HI + 19584)
#define SM4T   (SS_LO + 19584)   // 218624 bytes

__global__ __launch_bounds__(512) void k_out_mma(const float* __restrict__ vg,
                                                 float* __restrict__ outg) {
    extern __shared__ char smc[];
    const u32 sb = s2u(smc);
    float* den_s = (float*)(smc + OF_DEN);
    const int tid = threadIdx.x, wid = tid >> 5, lane = tid & 31;
    const int pid = wid & 7, half = wid >> 3;
    const int bid = blockIdx.x, bh = bid >> 5, c = bid & 31;
    const size_t tok0 = (size_t)bh * Nn + (size_t)c * CH;

    // ---- stage phi_q, phi_k ----
    const float* pqg = d_phiq + tok0 * Mm;
    const float* pkg = d_phik + tok0 * Mm;
    #pragma unroll
    for (int it = 0; it < 8; it++) {
        int idx = (it*512 + tid) * 4;
        int r = idx >> 7, cc = idx & 127;
        u32 off = (u32)r * SR + (u32)cc * 2;
        float4 t = *reinterpret_cast<const float4*>(pqg + idx);
        u16 h0,l0,h1,l1,h2,l2,h3,l3;
        split2(t.x,h0,l0); split2(t.y,h1,l1); split2(t.z,h2,l2); split2(t.w,h3,l3);
        *(u32*)(smc+SQ_HI+off)   = (u32)h0 | ((u32)h1<<16);
        *(u32*)(smc+SQ_HI+off+4) = (u32)h2 | ((u32)h3<<16);
        *(u32*)(smc+SQ_LO+off)   = (u32)l0 | ((u32)l1<<16);
        *(u32*)(smc+SQ_LO+off+4) = (u32)l2 | ((u32)l3<<16);
        t = *reinterpret_cast<const float4*>(pkg + idx);
        split2(t.x,h0,l0); split2(t.y,h1,l1); split2(t.z,h2,l2); split2(t.w,h3,l3);
        *(u32*)(smc+SK_HI+off)   = (u32)h0 | ((u32)h1<<16);
        *(u32*)(smc+SK_HI+off+4) = (u32)h2 | ((u32)h3<<16);
        *(u32*)(smc+SK_LO+off)   = (u32)l0 | ((u32)l1<<16);
        *(u32*)(smc+SK_LO+off+4) = (u32)l2 | ((u32)l3<<16);
    }

    // ---- stage VT [72][128] (transposed gather) ----
    #pragma unroll
    for (int it = 0; it < 2; it++) {
        int t4 = it*512 + tid;                 // 0..1023
        int jp = t4 >> 4, dg = (t4 & 15) << 2;
        float4 va = *reinterpret_cast<const float4*>(vg + (tok0 + 2*jp)*Dd + dg);
        float4 vb = *reinterpret_cast<const float4*>(vg + (tok0 + 2*jp + 1)*Dd + dg);
        float fa[4] = {va.x, va.y, va.z, va.w};
        float fb[4] = {vb.x, vb.y, vb.z, vb.w};
        #pragma unroll
        for (int e = 0; e < 4; e++) {
            u16 ha,la,hb,lb;
            split2(fa[e], ha, la); split2(fb[e], hb, lb);
            u32 off = (u32)(dg+e) * SR + (u32)jp * 4;
            *(u32*)(smc+SV_HI+off) = (u32)ha | ((u32)hb<<16);
            *(u32*)(smc+SV_LO+off) = (u32)la | ((u32)lb<<16);
        }
    }
    // ---- stage ST rows 0..63 directly from S^T gmem ----
    {
        const float* SgT = d_S + (size_t)(bh*NC + c) * (Mm*Dd);
        #pragma unroll
        for (int it = 0; it < 4; it++) {
            int idx = (it*512 + tid) * 4;      // 0..8191
            int d = idx >> 7, m = idx & 127;
            u32 off = (u32)d * SR + (u32)m * 2;
            float4 t = *reinterpret_cast<const float4*>(SgT + idx);
            u16 h0,l0,h1,l1,h2,l2,h3,l3;
            split2(t.x,h0,l0); split2(t.y,h1,l1); split2(t.z,h2,l2); split2(t.w,h3,l3);
            *(u32*)(smc+SS_HI+off)   = (u32)h0 | ((u32)h1<<16);
            *(u32*)(smc+SS_HI+off+4) = (u32)h2 | ((u32)h3<<16);
            *(u32*)(smc+SS_LO+off)   = (u32)l0 | ((u32)l1<<16);
            *(u32*)(smc+SS_LO+off+4) = (u32)l2 | ((u32)l3<<16);
        }
    }
    if (tid < 64) {
        int cp = tid * 2;
        u32 off = 64u * SR + (u32)tid * 4;
        *(u32*)(smc+SV_HI+off) = 0x3F803F80u;
        *(u32*)(smc+SV_LO+off) = 0u;
        const float* zg = d_zz + (bh*NC + c) * Mm;
        u16 h0,l0,h1,l1;
        split2(zg[cp],   h0, l0);
        split2(zg[cp+1], h1, l1);
        *(u32*)(smc+SS_HI+off) = (u32)h0 | ((u32)h1<<16);
        *(u32*)(smc+SS_LO+off) = (u32)l0 | ((u32)l1<<16);
    }
    for (int t4 = tid; t4 < 7*64; t4 += 512) {
        int r = 65 + t4/64;
        u32 off = (u32)r * SR + (u32)(t4 % 64) * 4;
        *(u32*)(smc+SV_HI+off) = 0u;
        *(u32*)(smc+SV_LO+off) = 0u;
        *(u32*)(smc+SS_HI+off) = 0u;
        *(u32*)(smc+SS_LO+off) = 0u;
    }
    __syncthreads();

    const int ib = (pid < 4) ? pid : (7 - (pid - 4));
    const int i0 = ib * 16;

    // ---- GEMM1 ----
    float acc[8][4];
    #pragma unroll
    for (int s = 0; s < 8; s++)
        #pragma unroll
        for (int e = 0; e < 4; e++) acc[s][e] = 0.f;

    for (int kk = 0; kk < 8; kk++) {
        int k0 = kk * 16;
        u32 qh0,qh1,qh2,qh3, ql0,ql1,ql2,ql3;
        ldsm4(qh0,qh1,qh2,qh3, a_addr(sb+SQ_HI, i0, k0, lane));
        ldsm4(ql0,ql1,ql2,ql3, a_addr(sb+SQ_LO, i0, k0, lane));
        #pragma unroll
        for (int s = 0; s < 4; s++) {
            int np = 2*s + half;
            if (np <= ib) {
                #pragma unroll
                for (int tt = 0; tt < 2; tt++) {
                    int nt = 2*np + tt;
                    u32 bh0,bh1, bl0,bl1;
                    ldsm2(bh0,bh1, b_addr(sb+SK_HI, nt*8, k0, lane));
                    ldsm2(bl0,bl1, b_addr(sb+SK_LO, nt*8, k0, lane));
                    mma16816(acc[2*s+tt], qh0,qh1,qh2,qh3, bh0,bh1);
                    mma16816(acc[2*s+tt], qh0,qh1,qh2,qh3, bl0,bl1);
                    mma16816(acc[2*s+tt], ql0,ql1,ql2,ql3, bh0,bh1);
                }
            }
        }
    }

    __syncthreads();

    // ---- mask + split + overwrite phik tiles ----
    {
        const int m1 = i0 + (lane >> 2);
        const int m2 = m1 + 8;
        #pragma unroll
        for (int s = 0; s < 4; s++) {
            int np = 2*s + half;
            if (np <= ib) {
                #pragma unroll
                for (int tt = 0; tt < 2; tt++) {
                    int nt = 2*np + tt;
                    int jj = nt*8 + 2*(lane & 3);
                    float a0 = (jj     <= m1) ? acc[2*s+tt][0] : 0.f;
                    float a1 = (jj + 1 <= m1) ? acc[2*s+tt][1] : 0.f;
                    float a2 = (jj     <= m2) ? acc[2*s+tt][2] : 0.f;
                    float a3 = (jj + 1 <= m2) ? acc[2*s+tt][3] : 0.f;
                    u16 h0,l0,h1,l1;
                    split2(a0, h0, l0); split2(a1, h1, l1);
                    u32 off = (u32)m1 * SR + (u32)jj * 2;
                    *(u32*)(smc+SK_HI+off) = (u32)h0 | ((u32)h1<<16);
                    *(u32*)(smc+SK_LO+off) = (u32)l0 | ((u32)l1<<16);
                    split2(a2, h0, l0); split2(a3, h1, l1);
                    off = (u32)m2 * SR + (u32)jj * 2;
                    *(u32*)(smc+SK_HI+off) = (u32)h0 | ((u32)h1<<16);
                    *(u32*)(smc+SK_LO+off) = (u32)l0 | ((u32)l1<<16);
                }
            }
        }
    }
    __syncthreads();

    // ---- GEMM2 ----
    float o[5][4];
    #pragma unroll
    for (int s = 0; s < 5; s++)
        #pragma unroll
        for (int e = 0; e < 4; e++) o[s][e] = 0.f;
    const int ntbase = half * 4;

    for (int kk = 0; kk < 8; kk++) {
        int k0 = kk * 16;
        u32 qh0,qh1,qh2,qh3, ql0,ql1,ql2,ql3;
        ldsm4(qh0,qh1,qh2,qh3, a_addr(sb+SQ_HI, i0, k0, lane));
        ldsm4(ql0,ql1,ql2,ql3, a_addr(sb+SQ_LO, i0, k0, lane));
        const bool doA = (kk <= ib);
        u32 ah0=0,ah1=0,ah2=0,ah3=0, al0=0,al1=0,al2=0,al3=0;
        if (doA) {
            ldsm4(ah0,ah1,ah2,ah3, a_addr(sb+SK_HI, i0, k0, lane));
            ldsm4(al0,al1,al2,al3, a_addr(sb+SK_LO, i0, k0, lane));
        }
        #pragma unroll
        for (int t = 0; t < 4; t++) {
            int nt = ntbase + t;
            u32 sh0,sh1, sl0,sl1;
            ldsm2(sh0,sh1, b_addr(sb+SS_HI, nt*8, k0, lane));
            ldsm2(sl0,sl1, b_addr(sb+SS_LO, nt*8, k0, lane));
            mma16816(o[t], qh0,qh1,qh2,qh3, sh0,sh1);
            mma16816(o[t], qh0,qh1,qh2,qh3, sl0,sl1);
            mma16816(o[t], ql0,ql1,ql2,ql3, sh0,sh1);
            if (doA) {
                u32 vh0,vh1, vl0,vl1;
                ldsm2(vh0,vh1, b_addr(sb+SV_HI, nt*8, k0, lane));
                ldsm2(vl0,vl1, b_addr(sb+SV_LO, nt*8, k0, lane));
                mma16816(o[t], ah0,ah1,ah2,ah3, vh0,vh1);
                mma16816(o[t], ah0,ah1,ah2,ah3, vl0,vl1);
                mma16816(o[t], al0,al1,al2,al3, vh0,vh1);
            }
        }
        if (half == 1) {
            u32 sh0,sh1, sl0,sl1;
            ldsm2(sh0,sh1, b_addr(sb+SS_HI, 64, k0, lane));
            ldsm2(sl0,sl1, b_addr(sb+SS_LO, 64, k0, lane));
            mma16816(o[4], qh0,qh1,qh2,qh3, sh0,sh1);
            mma16816(o[4], qh0,qh1,qh2,qh3, sl0,sl1);
            mma16816(o[4], ql0,ql1,ql2,ql3, sh0,sh1);
            if (doA) {
                u32 vh0,vh1, vl0,vl1;
                ldsm2(vh0,vh1, b_addr(sb+SV_HI, 64, k0, lane));
                ldsm2(vl0,vl1, b_addr(sb+SV_LO, 64, k0, lane));
                mma16816(o[4], ah0,ah1,ah2,ah3, vh0,vh1);
                mma16816(o[4], ah0,ah1,ah2,ah3, vl0,vl1);
                mma16816(o[4], al0,al1,al2,al3, vh0,vh1);
            }
        }
    }

    if (half == 1 && (lane & 3) == 0) {
        den_s[i0 + (lane >> 2)]     = 1.f / (o[4][0] + EPS_DEN);
        den_s[i0 + 8 + (lane >> 2)] = 1.f / (o[4][2] + EPS_DEN);
    }
    __syncthreads();
    {
        const int m1 = i0 + (lane >> 2);
        const int m2 = m1 + 8;
        const float inv1 = den_s[m1];
        const float inv2 = den_s[m2];
        #pragma unroll
        for (int t = 0; t < 4; t++) {
            int n = (ntbase + t)*8 + 2*(lane & 3);
            float2 t1 = { o[t][0]*inv1, o[t][1]*inv1 };
            float2 t2 = { o[t][2]*inv2, o[t][3]*inv2 };
            *reinterpret_cast<float2*>(outg + (tok0 + m1)*Dd + n) = t1;
            *reinterpret_cast<float2*>(outg + (tok0 + m2)*Dd + n) = t2;
        }
    }
}

// ---------------------------------------------------------------------------

extern "C" void kernel_launch(void* const* d_in, const int* in_sizes, int n_in,
                              void* d_out, int out_size) {
    const float* q  = (const float*)d_in[0];
    const float* k  = (const float*)d_in[1];
    const float* v  = (const float*)d_in[2];
    const float* om = (const float*)d_in[3];
    float* out = (float*)d_out;

    cudaFuncSetAttribute(k_proj_mma, cudaFuncAttributeMaxDynamicSharedMemorySize, SM1T);
    cudaFuncSetAttribute(k_sums_mma, cudaFuncAttributeMaxDynamicSharedMemorySize, SM2T);
    cudaFuncSetAttribute(k_out_mma,  cudaFuncAttributeMaxDynamicSharedMemorySize, SM4T);

    k_proj_mma<<<2*NBT, 256, SM1T>>>(q, k, om);
    k_gmax<<<1, 256>>>();
    k_sums_mma<<<NBT, 256, SM2T>>>(v);
    k_scan<<<2048 + 32, 256>>>();
    k_out_mma<<<NBT, 512, SM4T>>>(v, out);
}

// round 14
// speedup vs baseline: 1.2994x; 1.0213x over previous
#include <cuda_runtime.h>
#include <cuda_bf16.h>
#include <cstdint>

#define SCALE       0.35355339059327373f   // 64^(-1/4)
#define INV_SQRT_M  0.08838834764831843f   // 1/sqrt(128)
#define EPS_PHI     1e-4f
#define EPS_DEN     1e-6f

#define BH    64        // B*H = 4*16
#define Nn    4096
#define Dd    64
#define Mm    128
#define CH    128       // chunk length
#define NC    32        // chunks per head
#define NTOK  (BH*Nn)   // 262144
#define NBT   (NTOK/CH) // 2048 token-chunks

typedef unsigned long long u64;
typedef unsigned int u32;
typedef unsigned short u16;

// ---------------- warp MMA helpers ----------------
__device__ __forceinline__ u32 s2u(const void* p) {
    u32 a; asm("{ .reg .u64 t; cvta.to.shared.u64 t, %1; cvt.u32.u64 %0, t; }"
               : "=r"(a) : "l"(p));
    return a;
}
__device__ __forceinline__ void ldsm4(u32& r0, u32& r1, u32& r2, u32& r3, u32 addr) {
    asm volatile("ldmatrix.sync.aligned.m8n8.x4.shared.b16 {%0,%1,%2,%3}, [%4];"
                 : "=r"(r0), "=r"(r1), "=r"(r2), "=r"(r3) : "r"(addr));
}
__device__ __forceinline__ void ldsm2(u32& r0, u32& r1, u32 addr) {
    asm volatile("ldmatrix.sync.aligned.m8n8.x2.shared.b16 {%0,%1}, [%2];"
                 : "=r"(r0), "=r"(r1) : "r"(addr));
}
__device__ __forceinline__ void ldsm2t(u32& r0, u32& r1, u32 addr) {
    asm volatile("ldmatrix.sync.aligned.m8n8.x2.trans.shared.b16 {%0,%1}, [%2];"
                 : "=r"(r0), "=r"(r1) : "r"(addr));
}
__device__ __forceinline__ void mma16816(float* d, u32 a0, u32 a1, u32 a2, u32 a3,
                                         u32 b0, u32 b1) {
    asm volatile("mma.sync.aligned.m16n8k16.row.col.f32.bf16.bf16.f32 "
                 "{%0,%1,%2,%3}, {%4,%5,%6,%7}, {%8,%9}, {%0,%1,%2,%3};"
                 : "+f"(d[0]), "+f"(d[1]), "+f"(d[2]), "+f"(d[3])
                 : "r"(a0), "r"(a1), "r"(a2), "r"(a3), "r"(b0), "r"(b1));
}

// bf16 split
__device__ __forceinline__ u16 bf16h(float x) {
    u16 u; asm("cvt.rn.bf16.f32 %0, %1;" : "=h"(u) : "f"(x)); return u;
}
__device__ __forceinline__ float bf2f(u16 u) {
    float f; asm("cvt.f32.bf16 %0, %1;" : "=f"(f) : "h"(u)); return f;
}
__device__ __forceinline__ void split2(float x, u16& h, u16& l) {
    h = bf16h(x); l = bf16h(x - bf2f(h));
}

// Tile row strides (bytes): 136-half rows (K2/K4), 72-half rows (K1)
#define SR  272
#define SR1 144
__device__ __forceinline__ u32 a_addr_s(u32 base, int m0, int k0, int lane, int srb) {
    int r  = m0 + (lane & 7) + ((lane >> 3) & 1) * 8;
    int kc = k0 + (lane >> 4) * 8;
    return base + r * srb + kc * 2;
}
__device__ __forceinline__ u32 b_addr_s(u32 base, int n0, int k0, int lane, int srb) {
    int r  = n0 + (lane & 7);
    int kc = k0 + ((lane >> 3) & 1) * 8;
    return base + r * srb + kc * 2;
}
__device__ __forceinline__ u32 a_addr(u32 base, int m0, int k0, int lane) {
    return a_addr_s(base, m0, k0, lane, SR);
}
__device__ __forceinline__ u32 b_addr(u32 base, int n0, int k0, int lane) {
    return b_addr_s(base, n0, k0, lane, SR);
}
// trans-B address: storage [k][n] row-major; octet g in {0,1} -> stored rows
// k0+8g+l8 at byte col n0*2. Delivers B fragments [n][k] after HW transpose.
__device__ __forceinline__ u32 bt_addr(u32 base, int n0, int k0, int lane) {
    int l8 = lane & 7, g = (lane >> 3) & 1;
    return base + (u32)(k0 + g*8 + l8) * SR + (u32)n0 * 2;
}

// Scratch
__device__ float d_phiq[(size_t)NTOK*Mm];
__device__ float d_phik[(size_t)NTOK*Mm];   // lp ONLY (exp applied in K2/K4 staging)
__device__ float d_S[(size_t)BH*NC*Mm*Dd];  // S^T layout: [chunk][d=64][m=128]
__device__ float d_zz[BH*NC*Mm];
__device__ float d_bmax[NBT];
__device__ float d_gmax;

// ---------------------------------------------------------------------------
// K1 (warp-MMA): proj[128,128] = (x*scale)[128,64] @ omega^T  (exact R13)
// ---------------------------------------------------------------------------
#define P_SSP 0
#define P_SS  8192
#define P_RED 8704
#define P_XH  9728
#define P_XL  (P_XH + 18432)
#define P_OH  (P_XL + 18432)
#define P_OL  (P_OH + 18432)
#define SM1T  (P_OL + 18432)   // 83456 B

__global__ __launch_bounds__(256) void k_proj_mma(const float* __restrict__ qg,
                                                  const float* __restrict__ kg,
                                                  const float* __restrict__ omg) {
    extern __shared__ char smc[];
    const u32 sb = s2u(smc);
    float* ssp = (float*)(smc + P_SSP);
    float* ss  = (float*)(smc + P_SS);
    float* red = (float*)(smc + P_RED);

    const int bid = blockIdx.x;
    const bool isq = bid < NBT;
    const int tb  = isq ? bid : bid - NBT;
    const float* xg = (isq ? qg : kg) + (size_t)tb * CH * Dd;
    const int tid = threadIdx.x, wid = tid >> 5, lane = tid & 31;

    #pragma unroll
    for (int it = 0; it < 8; it++) {
        int f4g = it*256 + tid;
        int r = f4g >> 4, p = f4g & 15, c4 = p * 4;
        u32 off = (u32)r * SR1 + (u32)c4 * 2;
        float4 t = *reinterpret_cast<const float4*>(xg + r*Dd + c4);
        t.x *= SCALE; t.y *= SCALE; t.z *= SCALE; t.w *= SCALE;
        ssp[f4g] = t.x*t.x + t.y*t.y + t.z*t.z + t.w*t.w;
        u16 h0,l0,h1,l1,h2,l2,h3,l3;
        split2(t.x,h0,l0); split2(t.y,h1,l1); split2(t.z,h2,l2); split2(t.w,h3,l3);
        *(u32*)(smc+P_XH+off)   = (u32)h0 | ((u32)h1<<16);
        *(u32*)(smc+P_XH+off+4) = (u32)h2 | ((u32)h3<<16);
        *(u32*)(smc+P_XL+off)   = (u32)l0 | ((u32)l1<<16);
        *(u32*)(smc+P_XL+off+4) = (u32)l2 | ((u32)l3<<16);
        float4 w = *reinterpret_cast<const float4*>(omg + (size_t)f4g * 4);
        split2(w.x,h0,l0); split2(w.y,h1,l1); split2(w.z,h2,l2); split2(w.w,h3,l3);
        *(u32*)(smc+P_OH+off)   = (u32)h0 | ((u32)h1<<16);
        *(u32*)(smc+P_OH+off+4) = (u32)h2 | ((u32)h3<<16);
        *(u32*)(smc+P_OL+off)   = (u32)l0 | ((u32)l1<<16);
        *(u32*)(smc+P_OL+off+4) = (u32)l2 | ((u32)l3<<16);
    }
    __syncthreads();
    if (tid < 128) {
        float s = 0.f;
        #pragma unroll
        for (int j = 0; j < 16; j++) s += ssp[tid*16 + j];
        ss[tid] = 0.5f * s;
    }
    __syncthreads();

    const int i0 = wid * 16;
    float acc[16][4];
    #pragma unroll
    for (int nt = 0; nt < 16; nt++)
        #pragma unroll
        for (int e = 0; e < 4; e++) acc[nt][e] = 0.f;

    #pragma unroll
    for (int kk = 0; kk < 4; kk++) {
        int k0 = kk * 16;
        u32 xh0,xh1,xh2,xh3, xl0,xl1,xl2,xl3;
        ldsm4(xh0,xh1,xh2,xh3, a_addr_s(sb+P_XH, i0, k0, lane, SR1));
        ldsm4(xl0,xl1,xl2,xl3, a_addr_s(sb+P_XL, i0, k0, lane, SR1));
        #pragma unroll
        for (int nt = 0; nt < 16; nt++) {
            u32 oh0,oh1, ol0,ol1;
            ldsm2(oh0,oh1, b_addr_s(sb+P_OH, nt*8, k0, lane, SR1));
            ldsm2(ol0,ol1, b_addr_s(sb+P_OL, nt*8, k0, lane, SR1));
            mma16816(acc[nt], xh0,xh1,xh2,xh3, oh0,oh1);
            mma16816(acc[nt], xh0,xh1,xh2,xh3, ol0,ol1);
            mma16816(acc[nt], xl0,xl1,xl2,xl3, oh0,oh1);
        }
    }

    const int m1 = i0 + (lane >> 2);
    const int m2 = m1 + 8;
    const size_t tok0 = (size_t)tb * CH;

    if (isq) {
        float rm1 = -3.0e38f, rm2 = -3.0e38f;
        #pragma unroll
        for (int nt = 0; nt < 16; nt++) {
            rm1 = fmaxf(rm1, fmaxf(acc[nt][0], acc[nt][1]));
            rm2 = fmaxf(rm2, fmaxf(acc[nt][2], acc[nt][3]));
        }
        rm1 = fmaxf(rm1, __shfl_xor_sync(0xFFFFFFFFu, rm1, 1));
        rm1 = fmaxf(rm1, __shfl_xor_sync(0xFFFFFFFFu, rm1, 2));
        rm2 = fmaxf(rm2, __shfl_xor_sync(0xFFFFFFFFu, rm2, 1));
        rm2 = fmaxf(rm2, __shfl_xor_sync(0xFFFFFFFFu, rm2, 2));
        float* og = d_phiq + tok0 * Mm;
        #pragma unroll
        for (int nt = 0; nt < 16; nt++) {
            int jj = nt*8 + 2*(lane & 3);
            float2 t1, t2;
            t1.x = __expf(acc[nt][0]-rm1)*INV_SQRT_M + EPS_PHI;
            t1.y = __expf(acc[nt][1]-rm1)*INV_SQRT_M + EPS_PHI;
            t2.x = __expf(acc[nt][2]-rm2)*INV_SQRT_M + EPS_PHI;
            t2.y = __expf(acc[nt][3]-rm2)*INV_SQRT_M + EPS_PHI;
            *reinterpret_cast<float2*>(og + (size_t)m1*Mm + jj) = t1;
            *reinterpret_cast<float2*>(og + (size_t)m2*Mm + jj) = t2;
        }
    } else {
        const float s1 = ss[m1], s2 = ss[m2];
        float bm = -3.0e38f;
        float* og = d_phik + tok0 * Mm;
        #pragma unroll
        for (int nt = 0; nt < 16; nt++) {
            int jj = nt*8 + 2*(lane & 3);
            float2 t1, t2;
            t1.x = acc[nt][0] - s1; t1.y = acc[nt][1] - s1;
            t2.x = acc[nt][2] - s2; t2.y = acc[nt][3] - s2;
            bm = fmaxf(bm, fmaxf(fmaxf(t1.x, t1.y), fmaxf(t2.x, t2.y)));
            *reinterpret_cast<float2*>(og + (size_t)m1*Mm + jj) = t1;
            *reinterpret_cast<float2*>(og + (size_t)m2*Mm + jj) = t2;
        }
        red[tid] = bm;
        __syncthreads();
        for (int s = 128; s > 0; s >>= 1) {
            if (tid < s) red[tid] = fmaxf(red[tid], red[tid+s]);
            __syncthreads();
        }
        if (tid == 0) d_bmax[tb] = red[0];
    }
}

__global__ __launch_bounds__(256) void k_gmax() {
    __shared__ float red[256];
    const int tid = threadIdx.x;
    float m = -3.0e38f;
    for (int i = tid; i < NBT; i += 256) m = fmaxf(m, d_bmax[i]);
    red[tid] = m;
    __syncthreads();
    for (int s = 128; s > 0; s >>= 1) {
        if (tid < s) red[tid] = fmaxf(red[tid], red[tid+s]);
        __syncthreads();
    }
    if (tid == 0) d_gmax = red[0];
}

// ---------------------------------------------------------------------------
// K2 (warp-MMA): S^T[d,m] = sum_i V[i,d] * phik[i,m]. NO phik writeback —
// K4 recomputes exp from lp during staging (saves a 134 MB gmem stream).
// ---------------------------------------------------------------------------
#define Q_PKH 0
#define Q_PKL (Q_PKH + 34816)
#define Q_VTH (Q_PKL + 34816)
#define Q_VTL (Q_VTH + 17408)
#define Q_ZP  (Q_VTL + 17408)
#define SM2T  (Q_ZP + 1024)   // 105472 B

__global__ __launch_bounds__(256) void k_sums_mma(const float* __restrict__ vg) {
    extern __shared__ char smc[];
    const u32 sb = s2u(smc);
    float* zp = (float*)(smc + Q_ZP);
    const int tid = threadIdx.x, wid = tid >> 5, lane = tid & 31;
    const int bid = blockIdx.x, bh = bid >> 5, c = bid & 31;
    const size_t tok0 = (size_t)bh * Nn + (size_t)c * CH;
    const float gm = d_gmax;

    // ---- stage phik: exp + split into [i][m] tiles (no gmem writeback) ----
    const float* pk = d_phik + tok0 * Mm;   // lp
    #pragma unroll
    for (int it = 0; it < 16; it++) {
        int idx = (it*256 + tid) * 4;
        int i = idx >> 7, m = idx & 127;
        u32 off = (u32)i * SR + (u32)m * 2;
        float4 t = *reinterpret_cast<const float4*>(pk + idx);
        t.x = __expf(t.x-gm)*INV_SQRT_M + EPS_PHI;
        t.y = __expf(t.y-gm)*INV_SQRT_M + EPS_PHI;
        t.z = __expf(t.z-gm)*INV_SQRT_M + EPS_PHI;
        t.w = __expf(t.w-gm)*INV_SQRT_M + EPS_PHI;
        u16 h0,l0,h1,l1,h2,l2,h3,l3;
        split2(t.x,h0,l0); split2(t.y,h1,l1); split2(t.z,h2,l2); split2(t.w,h3,l3);
        *(u32*)(smc+Q_PKH+off)   = (u32)h0 | ((u32)h1<<16);
        *(u32*)(smc+Q_PKH+off+4) = (u32)h2 | ((u32)h3<<16);
        *(u32*)(smc+Q_PKL+off)   = (u32)l0 | ((u32)l1<<16);
        *(u32*)(smc+Q_PKL+off+4) = (u32)l2 | ((u32)l3<<16);
    }

    // ---- stage V^T [64][128] (transposed gather, split) ----
    #pragma unroll
    for (int it = 0; it < 4; it++) {
        int t4 = it*256 + tid;                 // 0..1023
        int jp = t4 >> 4, dg = (t4 & 15) << 2; // token pair, d-group
        float4 va = *reinterpret_cast<const float4*>(vg + (tok0 + 2*jp)*Dd + dg);
        float4 vb = *reinterpret_cast<const float4*>(vg + (tok0 + 2*jp + 1)*Dd + dg);
        float fa[4] = {va.x, va.y, va.z, va.w};
        float fb[4] = {vb.x, vb.y, vb.z, vb.w};
        #pragma unroll
        for (int e = 0; e < 4; e++) {
            u16 ha,la,hb,lb;
            split2(fa[e], ha, la); split2(fb[e], hb, lb);
            u32 off = (u32)(dg+e) * SR + (u32)jp * 4;
            *(u32*)(smc+Q_VTH+off) = (u32)ha | ((u32)hb<<16);
            *(u32*)(smc+Q_VTL+off) = (u32)la | ((u32)lb<<16);
        }
    }
    __syncthreads();

    // ---- z partials: thread t sums column m=t&127 over half the i rows ----
    {
        int m = tid & 127, ih = tid >> 7;
        float s = 0.f;
        int ibase = ih * 64;
        #pragma unroll 8
        for (int i = 0; i < 64; i++) {
            u32 off = (u32)(ibase + i) * SR + (u32)m * 2;
            u16 h = *(u16*)(smc+Q_PKH+off);
            u16 l = *(u16*)(smc+Q_PKL+off);
            s += bf2f(h) + bf2f(l);
        }
        zp[tid] = s;
    }
    __syncthreads();
    if (tid < 128) d_zz[(bh*NC + c)*Mm + tid] = zp[tid] + zp[tid + 128];

    // ---- GEMM: S^T = V^T . phik ----
    const int dt = wid >> 1, mh = wid & 1;
    const int d0 = dt * 16;
    float acc[8][4];
    #pragma unroll
    for (int t = 0; t < 8; t++)
        #pragma unroll
        for (int e = 0; e < 4; e++) acc[t][e] = 0.f;

    for (int kk = 0; kk < 8; kk++) {
        int k0 = kk * 16;
        u32 ah0,ah1,ah2,ah3, al0,al1,al2,al3;
        ldsm4(ah0,ah1,ah2,ah3, a_addr(sb+Q_VTH, d0, k0, lane));
        ldsm4(al0,al1,al2,al3, a_addr(sb+Q_VTL, d0, k0, lane));
        #pragma unroll
        for (int t = 0; t < 8; t++) {
            int n0 = (mh*8 + t) * 8;
            u32 bh0,bh1, bl0,bl1;
            ldsm2t(bh0,bh1, bt_addr(sb+Q_PKH, n0, k0, lane));
            ldsm2t(bl0,bl1, bt_addr(sb+Q_PKL, n0, k0, lane));
            mma16816(acc[t], ah0,ah1,ah2,ah3, bh0,bh1);
            mma16816(acc[t], ah0,ah1,ah2,ah3, bl0,bl1);
            mma16816(acc[t], al0,al1,al2,al3, bh0,bh1);
        }
    }

    // ---- write S^T [64][128] ----
    float* SgT = d_S + (size_t)(bh*NC + c) * (Mm*Dd);
    const int d1 = d0 + (lane >> 2), d2 = d1 + 8;
    #pragma unroll
    for (int t = 0; t < 8; t++) {
        int m = (mh*8 + t)*8 + 2*(lane & 3);
        float2 t1 = { acc[t][0], acc[t][1] };
        float2 t2 = { acc[t][2], acc[t][3] };
        *reinterpret_cast<float2*>(SgT + d1*Mm + m) = t1;
        *reinterpret_cast<float2*>(SgT + d2*Mm + m) = t2;
    }
}

// ---------------------------------------------------------------------------
// K3: exclusive prefix over the 32 chunks (unchanged)
// ---------------------------------------------------------------------------
__global__ __launch_bounds__(256) void k_scan() {
    const int gid = blockIdx.x * 256 + threadIdx.x;
    if (blockIdx.x < 2048) {
        const int bh = gid >> 13;
        const int e  = gid & 8191;
        const size_t p = (size_t)bh * NC * (Mm*Dd) + e;
        float v[NC];
        #pragma unroll
        for (int c = 0; c < NC; c++) v[c] = d_S[p + (size_t)c * (Mm*Dd)];
        float acc = 0.f;
        #pragma unroll
        for (int c = 0; c < NC; c++) {
            d_S[p + (size_t)c * (Mm*Dd)] = acc;
            acc += v[c];
        }
    } else {
        const int idx = gid - 2048*256;
        const int bh = idx >> 7, m = idx & 127;
        const size_t p = (size_t)bh * NC * Mm + m;
        float v[NC];
        #pragma unroll
        for (int c = 0; c < NC; c++) v[c] = d_zz[p + c*Mm];
        float acc = 0.f;
        #pragma unroll
        for (int c = 0; c < NC; c++) {
            d_zz[p + c*Mm] = acc;
            acc += v[c];
        }
    }
}

// ---------------------------------------------------------------------------
// K4 (warp-MMA, 512 threads): exact R13 except phik staging reads lp and
// applies exp(lp - gmax) itself.
// ---------------------------------------------------------------------------
#define OF_DEN 0
#define SQ_HI  1024
#define SQ_LO  (SQ_HI + 34816)
#define SK_HI  (SQ_LO + 34816)
#define SK_LO  (SK_HI + 34816)
#define SV_HI  (SK_LO + 34816)
#define SV_LO  (SV_HI + 19584)
#define SS_HI  (SV_LO + 19584)
#define SS_LO  (SS_HI + 19584)
#define SM4T   (SS_LO + 19584)   // 218624 bytes

__global__ __launch_bounds__(512) void k_out_mma(const float* __restrict__ vg,
                                                 float* __restrict__ outg) {
    extern __shared__ char smc[];
    const u32 sb = s2u(smc);
    float* den_s = (float*)(smc + OF_DEN);
    const int tid = threadIdx.x, wid = tid >> 5, lane = tid & 31;
    const int pid = wid & 7, half = wid >> 3;
    const int bid = blockIdx.x, bh = bid >> 5, c = bid & 31;
    const size_t tok0 = (size_t)bh * Nn + (size_t)c * CH;
    const float gm = d_gmax;

    // ---- stage phi_q (direct) and phi_k (exp from lp) ----
    const float* pqg = d_phiq + tok0 * Mm;
    const float* pkg = d_phik + tok0 * Mm;   // lp
    #pragma unroll
    for (int it = 0; it < 8; it++) {
        int idx = (it*512 + tid) * 4;
        int r = idx >> 7, cc = idx & 127;
        u32 off = (u32)r * SR + (u32)cc * 2;
        float4 t = *reinterpret_cast<const float4*>(pqg + idx);
        u16 h0,l0,h1,l1,h2,l2,h3,l3;
        split2(t.x,h0,l0); split2(t.y,h1,l1); split2(t.z,h2,l2); split2(t.w,h3,l3);
        *(u32*)(smc+SQ_HI+off)   = (u32)h0 | ((u32)h1<<16);
        *(u32*)(smc+SQ_HI+off+4) = (u32)h2 | ((u32)h3<<16);
        *(u32*)(smc+SQ_LO+off)   = (u32)l0 | ((u32)l1<<16);
        *(u32*)(smc+SQ_LO+off+4) = (u32)l2 | ((u32)l3<<16);
        t = *reinterpret_cast<const float4*>(pkg + idx);
        t.x = __expf(t.x-gm)*INV_SQRT_M + EPS_PHI;
        t.y = __expf(t.y-gm)*INV_SQRT_M + EPS_PHI;
        t.z = __expf(t.z-gm)*INV_SQRT_M + EPS_PHI;
        t.w = __expf(t.w-gm)*INV_SQRT_M + EPS_PHI;
        split2(t.x,h0,l0); split2(t.y,h1,l1); split2(t.z,h2,l2); split2(t.w,h3,l3);
        *(u32*)(smc+SK_HI+off)   = (u32)h0 | ((u32)h1<<16);
        *(u32*)(smc+SK_HI+off+4) = (u32)h2 | ((u32)h3<<16);
        *(u32*)(smc+SK_LO+off)   = (u32)l0 | ((u32)l1<<16);
        *(u32*)(smc+SK_LO+off+4) = (u32)l2 | ((u32)l3<<16);
    }

    // ---- stage VT [72][128] (transposed gather) ----
    #pragma unroll
    for (int it = 0; it < 2; it++) {
        int t4 = it*512 + tid;                 // 0..1023
        int jp = t4 >> 4, dg = (t4 & 15) << 2;
        float4 va = *reinterpret_cast<const float4*>(vg + (tok0 + 2*jp)*Dd + dg);
        float4 vb = *reinterpret_cast<const float4*>(vg + (tok0 + 2*jp + 1)*Dd + dg);
        float fa[4] = {va.x, va.y, va.z, va.w};
        float fb[4] = {vb.x, vb.y, vb.z, vb.w};
        #pragma unroll
        for (int e = 0; e < 4; e++) {
            u16 ha,la,hb,lb;
            split2(fa[e], ha, la); split2(fb[e], hb, lb);
            u32 off = (u32)(dg+e) * SR + (u32)jp * 4;
            *(u32*)(smc+SV_HI+off) = (u32)ha | ((u32)hb<<16);
            *(u32*)(smc+SV_LO+off) = (u32)la | ((u32)lb<<16);
        }
    }
    // ---- stage ST rows 0..63 directly from S^T gmem ----
    {
        const float* SgT = d_S + (size_t)(bh*NC + c) * (Mm*Dd);
        #pragma unroll
        for (int it = 0; it < 4; it++) {
            int idx = (it*512 + tid) * 4;      // 0..8191
            int d = idx >> 7, m = idx & 127;
            u32 off = (u32)d * SR + (u32)m * 2;
            float4 t = *reinterpret_cast<const float4*>(SgT + idx);
            u16 h0,l0,h1,l1,h2,l2,h3,l3;
            split2(t.x,h0,l0); split2(t.y,h1,l1); split2(t.z,h2,l2); split2(t.w,h3,l3);
            *(u32*)(smc+SS_HI+off)   = (u32)h0 | ((u32)h1<<16);
            *(u32*)(smc+SS_HI+off+4) = (u32)h2 | ((u32)h3<<16);
            *(u32*)(smc+SS_LO+off)   = (u32)l0 | ((u32)l1<<16);
            *(u32*)(smc+SS_LO+off+4) = (u32)l2 | ((u32)l3<<16);
        }
    }
    if (tid < 64) {
        int cp = tid * 2;
        u32 off = 64u * SR + (u32)tid * 4;
        *(u32*)(smc+SV_HI+off) = 0x3F803F80u;
        *(u32*)(smc+SV_LO+off) = 0u;
        const float* zg = d_zz + (bh*NC + c) * Mm;
        u16 h0,l0,h1,l1;
        split2(zg[cp],   h0, l0);
        split2(zg[cp+1], h1, l1);
        *(u32*)(smc+SS_HI+off) = (u32)h0 | ((u32)h1<<16);
        *(u32*)(smc+SS_LO+off) = (u32)l0 | ((u32)l1<<16);
    }
    for (int t4 = tid; t4 < 7*64; t4 += 512) {
        int r = 65 + t4/64;
        u32 off = (u32)r * SR + (u32)(t4 % 64) * 4;
        *(u32*)(smc+SV_HI+off) = 0u;
        *(u32*)(smc+SV_LO+off) = 0u;
        *(u32*)(smc+SS_HI+off) = 0u;
        *(u32*)(smc+SS_LO+off) = 0u;
    }
    __syncthreads();

    const int ib = (pid < 4) ? pid : (7 - (pid - 4));
    const int i0 = ib * 16;

    // ---- GEMM1 ----
    float acc[8][4];
    #pragma unroll
    for (int s = 0; s < 8; s++)
        #pragma unroll
        for (int e = 0; e < 4; e++) acc[s][e] = 0.f;

    for (int kk = 0; kk < 8; kk++) {
        int k0 = kk * 16;
        u32 qh0,qh1,qh2,qh3, ql0,ql1,ql2,ql3;
        ldsm4(qh0,qh1,qh2,qh3, a_addr(sb+SQ_HI, i0, k0, lane));
        ldsm4(ql0,ql1,ql2,ql3, a_addr(sb+SQ_LO, i0, k0, lane));
        #pragma unroll
        for (int s = 0; s < 4; s++) {
            int np = 2*s + half;
            if (np <= ib) {
                #pragma unroll
                for (int tt = 0; tt < 2; tt++) {
                    int nt = 2*np + tt;
                    u32 bh0,bh1, bl0,bl1;
                    ldsm2(bh0,bh1, b_addr(sb+SK_HI, nt*8, k0, lane));
                    ldsm2(bl0,bl1, b_addr(sb+SK_LO, nt*8, k0, lane));
                    mma16816(acc[2*s+tt], qh0,qh1,qh2,qh3, bh0,bh1);
                    mma16816(acc[2*s+tt], qh0,qh1,qh2,qh3, bl0,bl1);
                    mma16816(acc[2*s+tt], ql0,ql1,ql2,ql3, bh0,bh1);
                }
            }
        }
    }

    __syncthreads();

    // ---- mask + split + overwrite phik tiles ----
    {
        const int m1 = i0 + (lane >> 2);
        const int m2 = m1 + 8;
        #pragma unroll
        for (int s = 0; s < 4; s++) {
            int np = 2*s + half;
            if (np <= ib) {
                #pragma unroll
                for (int tt = 0; tt < 2; tt++) {
                    int nt = 2*np + tt;
                    int jj = nt*8 + 2*(lane & 3);
                    float a0 = (jj     <= m1) ? acc[2*s+tt][0] : 0.f;
                    float a1 = (jj + 1 <= m1) ? acc[2*s+tt][1] : 0.f;
                    float a2 = (jj     <= m2) ? acc[2*s+tt][2] : 0.f;
                    float a3 = (jj + 1 <= m2) ? acc[2*s+tt][3] : 0.f;
                    u16 h0,l0,h1,l1;
                    split2(a0, h0, l0); split2(a1, h1, l1);
                    u32 off = (u32)m1 * SR + (u32)jj * 2;
                    *(u32*)(smc+SK_HI+off) = (u32)h0 | ((u32)h1<<16);
                    *(u32*)(smc+SK_LO+off) = (u32)l0 | ((u32)l1<<16);
                    split2(a2, h0, l0); split2(a3, h1, l1);
                    off = (u32)m2 * SR + (u32)jj * 2;
                    *(u32*)(smc+SK_HI+off) = (u32)h0 | ((u32)h1<<16);
                    *(u32*)(smc+SK_LO+off) = (u32)l0 | ((u32)l1<<16);
                }
            }
        }
    }
    __syncthreads();

    // ---- GEMM2 ----
    float o[5][4];
    #pragma unroll
    for (int s = 0; s < 5; s++)
        #pragma unroll
        for (int e = 0; e < 4; e++) o[s][e] = 0.f;
    const int ntbase = half * 4;

    for (int kk = 0; kk < 8; kk++) {
        int k0 = kk * 16;
        u32 qh0,qh1,qh2,qh3, ql0,ql1,ql2,ql3;
        ldsm4(qh0,qh1,qh2,qh3, a_addr(sb+SQ_HI, i0, k0, lane));
        ldsm4(ql0,ql1,ql2,ql3, a_addr(sb+SQ_LO, i0, k0, lane));
        const bool doA = (kk <= ib);
        u32 ah0=0,ah1=0,ah2=0,ah3=0, al0=0,al1=0,al2=0,al3=0;
        if (doA) {
            ldsm4(ah0,ah1,ah2,ah3, a_addr(sb+SK_HI, i0, k0, lane));
            ldsm4(al0,al1,al2,al3, a_addr(sb+SK_LO, i0, k0, lane));
        }
        #pragma unroll
        for (int t = 0; t < 4; t++) {
            int nt = ntbase + t;
            u32 sh0,sh1, sl0,sl1;
            ldsm2(sh0,sh1, b_addr(sb+SS_HI, nt*8, k0, lane));
            ldsm2(sl0,sl1, b_addr(sb+SS_LO, nt*8, k0, lane));
            mma16816(o[t], qh0,qh1,qh2,qh3, sh0,sh1);
            mma16816(o[t], qh0,qh1,qh2,qh3, sl0,sl1);
            mma16816(o[t], ql0,ql1,ql2,ql3, sh0,sh1);
            if (doA) {
                u32 vh0,vh1, vl0,vl1;
                ldsm2(vh0,vh1, b_addr(sb+SV_HI, nt*8, k0, lane));
                ldsm2(vl0,vl1, b_addr(sb+SV_LO, nt*8, k0, lane));
                mma16816(o[t], ah0,ah1,ah2,ah3, vh0,vh1);
                mma16816(o[t], ah0,ah1,ah2,ah3, vl0,vl1);
                mma16816(o[t], al0,al1,al2,al3, vh0,vh1);
            }
        }
        if (half == 1) {
            u32 sh0,sh1, sl0,sl1;
            ldsm2(sh0,sh1, b_addr(sb+SS_HI, 64, k0, lane));
            ldsm2(sl0,sl1, b_addr(sb+SS_LO, 64, k0, lane));
            mma16816(o[4], qh0,qh1,qh2,qh3, sh0,sh1);
            mma16816(o[4], qh0,qh1,qh2,qh3, sl0,sl1);
            mma16816(o[4], ql0,ql1,ql2,ql3, sh0,sh1);
            if (doA) {
                u32 vh0,vh1, vl0,vl1;
                ldsm2(vh0,vh1, b_addr(sb+SV_HI, 64, k0, lane));
                ldsm2(vl0,vl1, b_addr(sb+SV_LO, 64, k0, lane));
                mma16816(o[4], ah0,ah1,ah2,ah3, vh0,vh1);
                mma16816(o[4], ah0,ah1,ah2,ah3, vl0,vl1);
                mma16816(o[4], al0,al1,al2,al3, vh0,vh1);
            }
        }
    }

    if (half == 1 && (lane & 3) == 0) {
        den_s[i0 + (lane >> 2)]     = 1.f / (o[4][0] + EPS_DEN);
        den_s[i0 + 8 + (lane >> 2)] = 1.f / (o[4][2] + EPS_DEN);
    }
    __syncthreads();
    {
        const int m1 = i0 + (lane >> 2);
        const int m2 = m1 + 8;
        const float inv1 = den_s[m1];
        const float inv2 = den_s[m2];
        #pragma unroll
        for (int t = 0; t < 4; t++) {
            int n = (ntbase + t)*8 + 2*(lane & 3);
            float2 t1 = { o[t][0]*inv1, o[t][1]*inv1 };
            float2 t2 = { o[t][2]*inv2, o[t][3]*inv2 };
            *reinterpret_cast<float2*>(outg + (tok0 + m1)*Dd + n) = t1;
            *reinterpret_cast<float2*>(outg + (tok0 + m2)*Dd + n) = t2;
        }
    }
}

// ---------------------------------------------------------------------------

extern "C" void kernel_launch(void* const* d_in, const int* in_sizes, int n_in,
                              void* d_out, int out_size) {
    const float* q  = (const float*)d_in[0];
    const float* k  = (const float*)d_in[1];
    const float* v  = (const float*)d_in[2];
    const float* om = (const float*)d_in[3];
    float* out = (float*)d_out;

    cudaFuncSetAttribute(k_proj_mma, cudaFuncAttributeMaxDynamicSharedMemorySize, SM1T);
    cudaFuncSetAttribute(k_sums_mma, cudaFuncAttributeMaxDynamicSharedMemorySize, SM2T);
    cudaFuncSetAttribute(k_out_mma,  cudaFuncAttributeMaxDynamicSharedMemorySize, SM4T);

    k_proj_mma<<<2*NBT, 256, SM1T>>>(q, k, om);
    k_gmax<<<1, 256>>>();
    k_sums_mma<<<NBT, 256, SM2T>>>(v);
    k_scan<<<2048 + 32, 256>>>();
    k_out_mma<<<NBT, 512, SM4T>>>(v, out);
}

// round 15
// speedup vs baseline: 1.3177x; 1.0141x over previous
#include <cuda_runtime.h>
#include <cuda_bf16.h>
#include <cstdint>

#define SCALE       0.35355339059327373f   // 64^(-1/4)
#define INV_SQRT_M  0.08838834764831843f   // 1/sqrt(128)
#define EPS_PHI     1e-4f
#define EPS_DEN     1e-6f

#define BH    64        // B*H = 4*16
#define Nn    4096
#define Dd    64
#define Mm    128
#define CH    128       // chunk length
#define NC    32        // chunks per head
#define NTOK  (BH*Nn)   // 262144
#define NBT   (NTOK/CH) // 2048 token-chunks

typedef unsigned long long u64;
typedef unsigned int u32;
typedef unsigned short u16;

// ---------------- warp MMA helpers ----------------
__device__ __forceinline__ u32 s2u(const void* p) {
    u32 a; asm("{ .reg .u64 t; cvta.to.shared.u64 t, %1; cvt.u32.u64 %0, t; }"
               : "=r"(a) : "l"(p));
    return a;
}
__device__ __forceinline__ void ldsm4(u32& r0, u32& r1, u32& r2, u32& r3, u32 addr) {
    asm volatile("ldmatrix.sync.aligned.m8n8.x4.shared.b16 {%0,%1,%2,%3}, [%4];"
                 : "=r"(r0), "=r"(r1), "=r"(r2), "=r"(r3) : "r"(addr));
}
__device__ __forceinline__ void ldsm2(u32& r0, u32& r1, u32 addr) {
    asm volatile("ldmatrix.sync.aligned.m8n8.x2.shared.b16 {%0,%1}, [%2];"
                 : "=r"(r0), "=r"(r1) : "r"(addr));
}
__device__ __forceinline__ void ldsm2t(u32& r0, u32& r1, u32 addr) {
    asm volatile("ldmatrix.sync.aligned.m8n8.x2.trans.shared.b16 {%0,%1}, [%2];"
                 : "=r"(r0), "=r"(r1) : "r"(addr));
}
__device__ __forceinline__ void mma16816(float* d, u32 a0, u32 a1, u32 a2, u32 a3,
                                         u32 b0, u32 b1) {
    asm volatile("mma.sync.aligned.m16n8k16.row.col.f32.bf16.bf16.f32 "
                 "{%0,%1,%2,%3}, {%4,%5,%6,%7}, {%8,%9}, {%0,%1,%2,%3};"
                 : "+f"(d[0]), "+f"(d[1]), "+f"(d[2]), "+f"(d[3])
                 : "r"(a0), "r"(a1), "r"(a2), "r"(a3), "r"(b0), "r"(b1));
}

// bf16 split
__device__ __forceinline__ u16 bf16h(float x) {
    u16 u; asm("cvt.rn.bf16.f32 %0, %1;" : "=h"(u) : "f"(x)); return u;
}
__device__ __forceinline__ float bf2f(u16 u) {
    float f; asm("cvt.f32.bf16 %0, %1;" : "=f"(f) : "h"(u)); return f;
}
__device__ __forceinline__ void split2(float x, u16& h, u16& l) {
    h = bf16h(x); l = bf16h(x - bf2f(h));
}

// Tile row strides (bytes): 136-half rows (K2/K4), 72-half rows (K1)
#define SR  272
#define SR1 144
__device__ __forceinline__ u32 a_addr_s(u32 base, int m0, int k0, int lane, int srb) {
    int r  = m0 + (lane & 7) + ((lane >> 3) & 1) * 8;
    int kc = k0 + (lane >> 4) * 8;
    return base + r * srb + kc * 2;
}
__device__ __forceinline__ u32 b_addr_s(u32 base, int n0, int k0, int lane, int srb) {
    int r  = n0 + (lane & 7);
    int kc = k0 + ((lane >> 3) & 1) * 8;
    return base + r * srb + kc * 2;
}
__device__ __forceinline__ u32 a_addr(u32 base, int m0, int k0, int lane) {
    return a_addr_s(base, m0, k0, lane, SR);
}
__device__ __forceinline__ u32 b_addr(u32 base, int n0, int k0, int lane) {
    return b_addr_s(base, n0, k0, lane, SR);
}
// trans-B address: storage [k][n] row-major; octet g in {0,1} -> stored rows
__device__ __forceinline__ u32 bt_addr(u32 base, int n0, int k0, int lane) {
    int l8 = lane & 7, g = (lane >> 3) & 1;
    return base + (u32)(k0 + g*8 + l8) * SR + (u32)n0 * 2;
}

// Scratch
__device__ float d_phik[(size_t)NTOK*Mm];   // lp ONLY (exp applied in K2/K4)
__device__ float d_S[(size_t)BH*NC*Mm*Dd];  // S^T layout: [chunk][d=64][m=128]
__device__ float d_zz[BH*NC*Mm];
__device__ float d_bmax[NBT];
__device__ float d_gmax;

// ---------------------------------------------------------------------------
// K1 (warp-MMA, k-only): lp[128,128] = (k*scale)@omega^T - 0.5||k*scale||^2
// ---------------------------------------------------------------------------
#define P_SSP 0
#define P_SS  8192
#define P_RED 8704
#define P_XH  9728
#define P_XL  (P_XH + 18432)
#define P_OH  (P_XL + 18432)
#define P_OL  (P_OH + 18432)
#define SM1T  (P_OL + 18432)   // 83456 B

__global__ __launch_bounds__(256) void k_proj_mma(const float* __restrict__ kg,
                                                  const float* __restrict__ omg) {
    extern __shared__ char smc[];
    const u32 sb = s2u(smc);
    float* ssp = (float*)(smc + P_SSP);
    float* ss  = (float*)(smc + P_SS);
    float* red = (float*)(smc + P_RED);

    const int tb = blockIdx.x;
    const float* xg = kg + (size_t)tb * CH * Dd;
    const int tid = threadIdx.x, wid = tid >> 5, lane = tid & 31;

    #pragma unroll
    for (int it = 0; it < 8; it++) {
        int f4g = it*256 + tid;
        int r = f4g >> 4, p = f4g & 15, c4 = p * 4;
        u32 off = (u32)r * SR1 + (u32)c4 * 2;
        float4 t = *reinterpret_cast<const float4*>(xg + r*Dd + c4);
        t.x *= SCALE; t.y *= SCALE; t.z *= SCALE; t.w *= SCALE;
        ssp[f4g] = t.x*t.x + t.y*t.y + t.z*t.z + t.w*t.w;
        u16 h0,l0,h1,l1,h2,l2,h3,l3;
        split2(t.x,h0,l0); split2(t.y,h1,l1); split2(t.z,h2,l2); split2(t.w,h3,l3);
        *(u32*)(smc+P_XH+off)   = (u32)h0 | ((u32)h1<<16);
        *(u32*)(smc+P_XH+off+4) = (u32)h2 | ((u32)h3<<16);
        *(u32*)(smc+P_XL+off)   = (u32)l0 | ((u32)l1<<16);
        *(u32*)(smc+P_XL+off+4) = (u32)l2 | ((u32)l3<<16);
        float4 w = *reinterpret_cast<const float4*>(omg + (size_t)f4g * 4);
        split2(w.x,h0,l0); split2(w.y,h1,l1); split2(w.z,h2,l2); split2(w.w,h3,l3);
        *(u32*)(smc+P_OH+off)   = (u32)h0 | ((u32)h1<<16);
        *(u32*)(smc+P_OH+off+4) = (u32)h2 | ((u32)h3<<16);
        *(u32*)(smc+P_OL+off)   = (u32)l0 | ((u32)l1<<16);
        *(u32*)(smc+P_OL+off+4) = (u32)l2 | ((u32)l3<<16);
    }
    __syncthreads();
    if (tid < 128) {
        float s = 0.f;
        #pragma unroll
        for (int j = 0; j < 16; j++) s += ssp[tid*16 + j];
        ss[tid] = 0.5f * s;
    }
    __syncthreads();

    const int i0 = wid * 16;
    float acc[16][4];
    #pragma unroll
    for (int nt = 0; nt < 16; nt++)
        #pragma unroll
        for (int e = 0; e < 4; e++) acc[nt][e] = 0.f;

    #pragma unroll
    for (int kk = 0; kk < 4; kk++) {
        int k0 = kk * 16;
        u32 xh0,xh1,xh2,xh3, xl0,xl1,xl2,xl3;
        ldsm4(xh0,xh1,xh2,xh3, a_addr_s(sb+P_XH, i0, k0, lane, SR1));
        ldsm4(xl0,xl1,xl2,xl3, a_addr_s(sb+P_XL, i0, k0, lane, SR1));
        #pragma unroll
        for (int nt = 0; nt < 16; nt++) {
            u32 oh0,oh1, ol0,ol1;
            ldsm2(oh0,oh1, b_addr_s(sb+P_OH, nt*8, k0, lane, SR1));
            ldsm2(ol0,ol1, b_addr_s(sb+P_OL, nt*8, k0, lane, SR1));
            mma16816(acc[nt], xh0,xh1,xh2,xh3, oh0,oh1);
            mma16816(acc[nt], xh0,xh1,xh2,xh3, ol0,ol1);
            mma16816(acc[nt], xl0,xl1,xl2,xl3, oh0,oh1);
        }
    }

    const int m1 = i0 + (lane >> 2);
    const int m2 = m1 + 8;
    const size_t tok0 = (size_t)tb * CH;

    const float s1 = ss[m1], s2 = ss[m2];
    float bm = -3.0e38f;
    float* og = d_phik + tok0 * Mm;
    #pragma unroll
    for (int nt = 0; nt < 16; nt++) {
        int jj = nt*8 + 2*(lane & 3);
        float2 t1, t2;
        t1.x = acc[nt][0] - s1; t1.y = acc[nt][1] - s1;
        t2.x = acc[nt][2] - s2; t2.y = acc[nt][3] - s2;
        bm = fmaxf(bm, fmaxf(fmaxf(t1.x, t1.y), fmaxf(t2.x, t2.y)));
        *reinterpret_cast<float2*>(og + (size_t)m1*Mm + jj) = t1;
        *reinterpret_cast<float2*>(og + (size_t)m2*Mm + jj) = t2;
    }
    red[tid] = bm;
    __syncthreads();
    for (int s = 128; s > 0; s >>= 1) {
        if (tid < s) red[tid] = fmaxf(red[tid], red[tid+s]);
        __syncthreads();
    }
    if (tid == 0) d_bmax[tb] = red[0];
}

__global__ __launch_bounds__(256) void k_gmax() {
    __shared__ float red[256];
    const int tid = threadIdx.x;
    float m = -3.0e38f;
    for (int i = tid; i < NBT; i += 256) m = fmaxf(m, d_bmax[i]);
    red[tid] = m;
    __syncthreads();
    for (int s = 128; s > 0; s >>= 1) {
        if (tid < s) red[tid] = fmaxf(red[tid], red[tid+s]);
        __syncthreads();
    }
    if (tid == 0) d_gmax = red[0];
}

// ---------------------------------------------------------------------------
// K2 (warp-MMA): S^T[d,m] = sum_i V[i,d] * phik[i,m]  (exact R14)
// ---------------------------------------------------------------------------
#define Q_PKH 0
#define Q_PKL (Q_PKH + 34816)
#define Q_VTH (Q_PKL + 34816)
#define Q_VTL (Q_VTH + 17408)
#define Q_ZP  (Q_VTL + 17408)
#define SM2T  (Q_ZP + 1024)   // 105472 B

__global__ __launch_bounds__(256) void k_sums_mma(const float* __restrict__ vg) {
    extern __shared__ char smc[];
    const u32 sb = s2u(smc);
    float* zp = (float*)(smc + Q_ZP);
    const int tid = threadIdx.x, wid = tid >> 5, lane = tid & 31;
    const int bid = blockIdx.x, bh = bid >> 5, c = bid & 31;
    const size_t tok0 = (size_t)bh * Nn + (size_t)c * CH;
    const float gm = d_gmax;

    const float* pk = d_phik + tok0 * Mm;   // lp
    #pragma unroll
    for (int it = 0; it < 16; it++) {
        int idx = (it*256 + tid) * 4;
        int i = idx >> 7, m = idx & 127;
        u32 off = (u32)i * SR + (u32)m * 2;
        float4 t = *reinterpret_cast<const float4*>(pk + idx);
        t.x = __expf(t.x-gm)*INV_SQRT_M + EPS_PHI;
        t.y = __expf(t.y-gm)*INV_SQRT_M + EPS_PHI;
        t.z = __expf(t.z-gm)*INV_SQRT_M + EPS_PHI;
        t.w = __expf(t.w-gm)*INV_SQRT_M + EPS_PHI;
        u16 h0,l0,h1,l1,h2,l2,h3,l3;
        split2(t.x,h0,l0); split2(t.y,h1,l1); split2(t.z,h2,l2); split2(t.w,h3,l3);
        *(u32*)(smc+Q_PKH+off)   = (u32)h0 | ((u32)h1<<16);
        *(u32*)(smc+Q_PKH+off+4) = (u32)h2 | ((u32)h3<<16);
        *(u32*)(smc+Q_PKL+off)   = (u32)l0 | ((u32)l1<<16);
        *(u32*)(smc+Q_PKL+off+4) = (u32)l2 | ((u32)l3<<16);
    }

    #pragma unroll
    for (int it = 0; it < 4; it++) {
        int t4 = it*256 + tid;
        int jp = t4 >> 4, dg = (t4 & 15) << 2;
        float4 va = *reinterpret_cast<const float4*>(vg + (tok0 + 2*jp)*Dd + dg);
        float4 vb = *reinterpret_cast<const float4*>(vg + (tok0 + 2*jp + 1)*Dd + dg);
        float fa[4] = {va.x, va.y, va.z, va.w};
        float fb[4] = {vb.x, vb.y, vb.z, vb.w};
        #pragma unroll
        for (int e = 0; e < 4; e++) {
            u16 ha,la,hb,lb;
            split2(fa[e], ha, la); split2(fb[e], hb, lb);
            u32 off = (u32)(dg+e) * SR + (u32)jp * 4;
            *(u32*)(smc+Q_VTH+off) = (u32)ha | ((u32)hb<<16);
            *(u32*)(smc+Q_VTL+off) = (u32)la | ((u32)lb<<16);
        }
    }
    __syncthreads();

    {
        int m = tid & 127, ih = tid >> 7;
        float s = 0.f;
        int ibase = ih * 64;
        #pragma unroll 8
        for (int i = 0; i < 64; i++) {
            u32 off = (u32)(ibase + i) * SR + (u32)m * 2;
            u16 h = *(u16*)(smc+Q_PKH+off);
            u16 l = *(u16*)(smc+Q_PKL+off);
            s += bf2f(h) + bf2f(l);
        }
        zp[tid] = s;
    }
    __syncthreads();
    if (tid < 128) d_zz[(bh*NC + c)*Mm + tid] = zp[tid] + zp[tid + 128];

    const int dt = wid >> 1, mh = wid & 1;
    const int d0 = dt * 16;
    float acc[8][4];
    #pragma unroll
    for (int t = 0; t < 8; t++)
        #pragma unroll
        for (int e = 0; e < 4; e++) acc[t][e] = 0.f;

    for (int kk = 0; kk < 8; kk++) {
        int k0 = kk * 16;
        u32 ah0,ah1,ah2,ah3, al0,al1,al2,al3;
        ldsm4(ah0,ah1,ah2,ah3, a_addr(sb+Q_VTH, d0, k0, lane));
        ldsm4(al0,al1,al2,al3, a_addr(sb+Q_VTL, d0, k0, lane));
        #pragma unroll
        for (int t = 0; t < 8; t++) {
            int n0 = (mh*8 + t) * 8;
            u32 bh0,bh1, bl0,bl1;
            ldsm2t(bh0,bh1, bt_addr(sb+Q_PKH, n0, k0, lane));
            ldsm2t(bl0,bl1, bt_addr(sb+Q_PKL, n0, k0, lane));
            mma16816(acc[t], ah0,ah1,ah2,ah3, bh0,bh1);
            mma16816(acc[t], ah0,ah1,ah2,ah3, bl0,bl1);
            mma16816(acc[t], al0,al1,al2,al3, bh0,bh1);
        }
    }

    float* SgT = d_S + (size_t)(bh*NC + c) * (Mm*Dd);
    const int d1 = d0 + (lane >> 2), d2 = d1 + 8;
    #pragma unroll
    for (int t = 0; t < 8; t++) {
        int m = (mh*8 + t)*8 + 2*(lane & 3);
        float2 t1 = { acc[t][0], acc[t][1] };
        float2 t2 = { acc[t][2], acc[t][3] };
        *reinterpret_cast<float2*>(SgT + d1*Mm + m) = t1;
        *reinterpret_cast<float2*>(SgT + d2*Mm + m) = t2;
    }
}

// ---------------------------------------------------------------------------
// K3: exclusive prefix over the 32 chunks (unchanged)
// ---------------------------------------------------------------------------
__global__ __launch_bounds__(256) void k_scan() {
    const int gid = blockIdx.x * 256 + threadIdx.x;
    if (blockIdx.x < 2048) {
        const int bh = gid >> 13;
        const int e  = gid & 8191;
        const size_t p = (size_t)bh * NC * (Mm*Dd) + e;
        float v[NC];
        #pragma unroll
        for (int c = 0; c < NC; c++) v[c] = d_S[p + (size_t)c * (Mm*Dd)];
        float acc = 0.f;
        #pragma unroll
        for (int c = 0; c < NC; c++) {
            d_S[p + (size_t)c * (Mm*Dd)] = acc;
            acc += v[c];
        }
    } else {
        const int idx = gid - 2048*256;
        const int bh = idx >> 7, m = idx & 127;
        const size_t p = (size_t)bh * NC * Mm + m;
        float v[NC];
        #pragma unroll
        for (int c = 0; c < NC; c++) v[c] = d_zz[p + c*Mm];
        float acc = 0.f;
        #pragma unroll
        for (int c = 0; c < NC; c++) {
            d_zz[p + c*Mm] = acc;
            acc += v[c];
        }
    }
}

// ---------------------------------------------------------------------------
// K4 (warp-MMA, 512 threads): q-projection FUSED.
//  A: stage q*scale -> SQ tiles, omega -> SK tiles
//  B: proj GEMM -> rowmax (quad shuffle + smem half-exchange) -> exp ->
//     phi_q split written over SQ tiles
//  C: stage lp->exp->SK (overwrites omega), V->SV, S^T->SS, z/ones rows
//  D: GEMM1 (causal) -> mask -> A into SK -> GEMM2 -> out
// ---------------------------------------------------------------------------
#define OF_RM  0      // 1024 B: rowmax exchange, later den
#define SQ_HI  1024
#define SQ_LO  (SQ_HI + 34816)
#define SK_HI  (SQ_LO + 34816)
#define SK_LO  (SK_HI + 34816)
#define SV_HI  (SK_LO + 34816)
#define SV_LO  (SV_HI + 19584)
#define SS_HI  (SV_LO + 19584)
#define SS_LO  (SS_HI + 19584)
#define SM4T   (SS_LO + 19584)   // 218624 bytes

__global__ __launch_bounds__(512) void k_out_mma(const float* __restrict__ qg,
                                                 const float* __restrict__ omg,
                                                 const float* __restrict__ vg,
                                                 float* __restrict__ outg) {
    extern __shared__ char smc[];
    const u32 sb = s2u(smc);
    float* rm_s  = (float*)(smc + OF_RM);   // [128][2] halves, then den[128]
    const int tid = threadIdx.x, wid = tid >> 5, lane = tid & 31;
    const int pid = wid & 7, half = wid >> 3;
    const int bid = blockIdx.x, bh = bid >> 5, c = bid & 31;
    const size_t tok0 = (size_t)bh * Nn + (size_t)c * CH;
    const float gm = d_gmax;

    // ---- phase A: stage q (scaled, split) -> SQ; omega -> SK ----
    const float* xg = qg + tok0 * Dd;
    #pragma unroll
    for (int it = 0; it < 4; it++) {
        int f4g = it*512 + tid;                // 0..2047 float4s
        int r = f4g >> 4, c4 = (f4g & 15) * 4; // row, d-col
        u32 off = (u32)r * SR + (u32)c4 * 2;
        float4 t = *reinterpret_cast<const float4*>(xg + r*Dd + c4);
        t.x *= SCALE; t.y *= SCALE; t.z *= SCALE; t.w *= SCALE;
        u16 h0,l0,h1,l1,h2,l2,h3,l3;
        split2(t.x,h0,l0); split2(t.y,h1,l1); split2(t.z,h2,l2); split2(t.w,h3,l3);
        *(u32*)(smc+SQ_HI+off)   = (u32)h0 | ((u32)h1<<16);
        *(u32*)(smc+SQ_HI+off+4) = (u32)h2 | ((u32)h3<<16);
        *(u32*)(smc+SQ_LO+off)   = (u32)l0 | ((u32)l1<<16);
        *(u32*)(smc+SQ_LO+off+4) = (u32)l2 | ((u32)l3<<16);
        float4 w = *reinterpret_cast<const float4*>(omg + (size_t)f4g * 4);
        split2(w.x,h0,l0); split2(w.y,h1,l1); split2(w.z,h2,l2); split2(w.w,h3,l3);
        *(u32*)(smc+SK_HI+off)   = (u32)h0 | ((u32)h1<<16);
        *(u32*)(smc+SK_HI+off+4) = (u32)h2 | ((u32)h3<<16);
        *(u32*)(smc+SK_LO+off)   = (u32)l0 | ((u32)l1<<16);
        *(u32*)(smc+SK_LO+off+4) = (u32)l2 | ((u32)l3<<16);
    }
    __syncthreads();

    // ---- phase B: proj GEMM (rows pid*16, m-half = half*64) ----
    {
        const int prow = pid * 16;
        float pacc[8][4];
        #pragma unroll
        for (int t = 0; t < 8; t++)
            #pragma unroll
            for (int e = 0; e < 4; e++) pacc[t][e] = 0.f;

        #pragma unroll
        for (int kk = 0; kk < 4; kk++) {
            int k0 = kk * 16;
            u32 xh0,xh1,xh2,xh3, xl0,xl1,xl2,xl3;
            ldsm4(xh0,xh1,xh2,xh3, a_addr(sb+SQ_HI, prow, k0, lane));
            ldsm4(xl0,xl1,xl2,xl3, a_addr(sb+SQ_LO, prow, k0, lane));
            #pragma unroll
            for (int t = 0; t < 8; t++) {
                int nt = half*8 + t;
                u32 oh0,oh1, ol0,ol1;
                ldsm2(oh0,oh1, b_addr(sb+SK_HI, nt*8, k0, lane));
                ldsm2(ol0,ol1, b_addr(sb+SK_LO, nt*8, k0, lane));
                mma16816(pacc[t], xh0,xh1,xh2,xh3, oh0,oh1);
                mma16816(pacc[t], xh0,xh1,xh2,xh3, ol0,ol1);
                mma16816(pacc[t], xl0,xl1,xl2,xl3, oh0,oh1);
            }
        }

        const int m1 = prow + (lane >> 2);
        const int m2 = m1 + 8;
        float rm1 = -3.0e38f, rm2 = -3.0e38f;
        #pragma unroll
        for (int t = 0; t < 8; t++) {
            rm1 = fmaxf(rm1, fmaxf(pacc[t][0], pacc[t][1]));
            rm2 = fmaxf(rm2, fmaxf(pacc[t][2], pacc[t][3]));
        }
        rm1 = fmaxf(rm1, __shfl_xor_sync(0xFFFFFFFFu, rm1, 1));
        rm1 = fmaxf(rm1, __shfl_xor_sync(0xFFFFFFFFu, rm1, 2));
        rm2 = fmaxf(rm2, __shfl_xor_sync(0xFFFFFFFFu, rm2, 1));
        rm2 = fmaxf(rm2, __shfl_xor_sync(0xFFFFFFFFu, rm2, 2));
        if ((lane & 3) == 0) {
            rm_s[m1*2 + half] = rm1;
            rm_s[m2*2 + half] = rm2;
        }
        __syncthreads();
        rm1 = fmaxf(rm_s[m1*2], rm_s[m1*2 + 1]);
        rm2 = fmaxf(rm_s[m2*2], rm_s[m2*2 + 1]);

        // exp -> phi_q split, overwrite SQ tiles (own rows/cols only)
        #pragma unroll
        for (int t = 0; t < 8; t++) {
            int jj = (half*8 + t)*8 + 2*(lane & 3);
            float p0 = __expf(pacc[t][0]-rm1)*INV_SQRT_M + EPS_PHI;
            float p1 = __expf(pacc[t][1]-rm1)*INV_SQRT_M + EPS_PHI;
            float p2 = __expf(pacc[t][2]-rm2)*INV_SQRT_M + EPS_PHI;
            float p3 = __expf(pacc[t][3]-rm2)*INV_SQRT_M + EPS_PHI;
            u16 h0,l0,h1,l1;
            split2(p0, h0, l0); split2(p1, h1, l1);
            u32 off = (u32)m1 * SR + (u32)jj * 2;
            *(u32*)(smc+SQ_HI+off) = (u32)h0 | ((u32)h1<<16);
            *(u32*)(smc+SQ_LO+off) = (u32)l0 | ((u32)l1<<16);
            split2(p2, h0, l0); split2(p3, h1, l1);
            off = (u32)m2 * SR + (u32)jj * 2;
            *(u32*)(smc+SQ_HI+off) = (u32)h0 | ((u32)h1<<16);
            *(u32*)(smc+SQ_LO+off) = (u32)l0 | ((u32)l1<<16);
        }
    }
    __syncthreads();   // omega reads + phi_q writes complete

    // ---- phase C: stage phi_k (exp from lp) -> SK, V -> SV, S^T -> SS ----
    const float* pkg = d_phik + tok0 * Mm;
    #pragma unroll
    for (int it = 0; it < 8; it++) {
        int idx = (it*512 + tid) * 4;
        int r = idx >> 7, cc = idx & 127;
        u32 off = (u32)r * SR + (u32)cc * 2;
        float4 t = *reinterpret_cast<const float4*>(pkg + idx);
        t.x = __expf(t.x-gm)*INV_SQRT_M + EPS_PHI;
        t.y = __expf(t.y-gm)*INV_SQRT_M + EPS_PHI;
        t.z = __expf(t.z-gm)*INV_SQRT_M + EPS_PHI;
        t.w = __expf(t.w-gm)*INV_SQRT_M + EPS_PHI;
        u16 h0,l0,h1,l1,h2,l2,h3,l3;
        split2(t.x,h0,l0); split2(t.y,h1,l1); split2(t.z,h2,l2); split2(t.w,h3,l3);
        *(u32*)(smc+SK_HI+off)   = (u32)h0 | ((u32)h1<<16);
        *(u32*)(smc+SK_HI+off+4) = (u32)h2 | ((u32)h3<<16);
        *(u32*)(smc+SK_LO+off)   = (u32)l0 | ((u32)l1<<16);
        *(u32*)(smc+SK_LO+off+4) = (u32)l2 | ((u32)l3<<16);
    }

    #pragma unroll
    for (int it = 0; it < 2; it++) {
        int t4 = it*512 + tid;
        int jp = t4 >> 4, dg = (t4 & 15) << 2;
        float4 va = *reinterpret_cast<const float4*>(vg + (tok0 + 2*jp)*Dd + dg);
        float4 vb = *reinterpret_cast<const float4*>(vg + (tok0 + 2*jp + 1)*Dd + dg);
        float fa[4] = {va.x, va.y, va.z, va.w};
        float fb[4] = {vb.x, vb.y, vb.z, vb.w};
        #pragma unroll
        for (int e = 0; e < 4; e++) {
            u16 ha,la,hb,lb;
            split2(fa[e], ha, la); split2(fb[e], hb, lb);
            u32 off = (u32)(dg+e) * SR + (u32)jp * 4;
            *(u32*)(smc+SV_HI+off) = (u32)ha | ((u32)hb<<16);
            *(u32*)(smc+SV_LO+off) = (u32)la | ((u32)lb<<16);
        }
    }
    {
        const float* SgT = d_S + (size_t)(bh*NC + c) * (Mm*Dd);
        #pragma unroll
        for (int it = 0; it < 4; it++) {
            int idx = (it*512 + tid) * 4;
            int d = idx >> 7, m = idx & 127;
            u32 off = (u32)d * SR + (u32)m * 2;
            float4 t = *reinterpret_cast<const float4*>(SgT + idx);
            u16 h0,l0,h1,l1,h2,l2,h3,l3;
            split2(t.x,h0,l0); split2(t.y,h1,l1); split2(t.z,h2,l2); split2(t.w,h3,l3);
            *(u32*)(smc+SS_HI+off)   = (u32)h0 | ((u32)h1<<16);
            *(u32*)(smc+SS_HI+off+4) = (u32)h2 | ((u32)h3<<16);
            *(u32*)(smc+SS_LO+off)   = (u32)l0 | ((u32)l1<<16);
            *(u32*)(smc+SS_LO+off+4) = (u32)l2 | ((u32)l3<<16);
        }
    }
    if (tid < 64) {
        int cp = tid * 2;
        u32 off = 64u * SR + (u32)tid * 4;
        *(u32*)(smc+SV_HI+off) = 0x3F803F80u;
        *(u32*)(smc+SV_LO+off) = 0u;
        const float* zg = d_zz + (bh*NC + c) * Mm;
        u16 h0,l0,h1,l1;
        split2(zg[cp],   h0, l0);
        split2(zg[cp+1], h1, l1);
        *(u32*)(smc+SS_HI+off) = (u32)h0 | ((u32)h1<<16);
        *(u32*)(smc+SS_LO+off) = (u32)l0 | ((u32)l1<<16);
    }
    for (int t4 = tid; t4 < 7*64; t4 += 512) {
        int r = 65 + t4/64;
        u32 off = (u32)r * SR + (u32)(t4 % 64) * 4;
        *(u32*)(smc+SV_HI+off) = 0u;
        *(u32*)(smc+SV_LO+off) = 0u;
        *(u32*)(smc+SS_HI+off) = 0u;
        *(u32*)(smc+SS_LO+off) = 0u;
    }
    __syncthreads();

    const int ib = (pid < 4) ? pid : (7 - (pid - 4));
    const int i0 = ib * 16;

    // ---- GEMM1 ----
    float acc[8][4];
    #pragma unroll
    for (int s = 0; s < 8; s++)
        #pragma unroll
        for (int e = 0; e < 4; e++) acc[s][e] = 0.f;

    for (int kk = 0; kk < 8; kk++) {
        int k0 = kk * 16;
        u32 qh0,qh1,qh2,qh3, ql0,ql1,ql2,ql3;
        ldsm4(qh0,qh1,qh2,qh3, a_addr(sb+SQ_HI, i0, k0, lane));
        ldsm4(ql0,ql1,ql2,ql3, a_addr(sb+SQ_LO, i0, k0, lane));
        #pragma unroll
        for (int s = 0; s < 4; s++) {
            int np = 2*s + half;
            if (np <= ib) {
                #pragma unroll
                for (int tt = 0; tt < 2; tt++) {
                    int nt = 2*np + tt;
                    u32 bh0,bh1, bl0,bl1;
                    ldsm2(bh0,bh1, b_addr(sb+SK_HI, nt*8, k0, lane));
                    ldsm2(bl0,bl1, b_addr(sb+SK_LO, nt*8, k0, lane));
                    mma16816(acc[2*s+tt], qh0,qh1,qh2,qh3, bh0,bh1);
                    mma16816(acc[2*s+tt], qh0,qh1,qh2,qh3, bl0,bl1);
                    mma16816(acc[2*s+tt], ql0,ql1,ql2,ql3, bh0,bh1);
                }
            }
        }
    }

    __syncthreads();

    // ---- mask + split + overwrite phik tiles ----
    {
        const int m1 = i0 + (lane >> 2);
        const int m2 = m1 + 8;
        #pragma unroll
        for (int s = 0; s < 4; s++) {
            int np = 2*s + half;
            if (np <= ib) {
                #pragma unroll
                for (int tt = 0; tt < 2; tt++) {
                    int nt = 2*np + tt;
                    int jj = nt*8 + 2*(lane & 3);
                    float a0 = (jj     <= m1) ? acc[2*s+tt][0] : 0.f;
                    float a1 = (jj + 1 <= m1) ? acc[2*s+tt][1] : 0.f;
                    float a2 = (jj     <= m2) ? acc[2*s+tt][2] : 0.f;
                    float a3 = (jj + 1 <= m2) ? acc[2*s+tt][3] : 0.f;
                    u16 h0,l0,h1,l1;
                    split2(a0, h0, l0); split2(a1, h1, l1);
                    u32 off = (u32)m1 * SR + (u32)jj * 2;
                    *(u32*)(smc+SK_HI+off) = (u32)h0 | ((u32)h1<<16);
                    *(u32*)(smc+SK_LO+off) = (u32)l0 | ((u32)l1<<16);
                    split2(a2, h0, l0); split2(a3, h1, l1);
                    off = (u32)m2 * SR + (u32)jj * 2;
                    *(u32*)(smc+SK_HI+off) = (u32)h0 | ((u32)h1<<16);
                    *(u32*)(smc+SK_LO+off) = (u32)l0 | ((u32)l1<<16);
                }
            }
        }
    }
    __syncthreads();

    // ---- GEMM2 ----
    float o[5][4];
    #pragma unroll
    for (int s = 0; s < 5; s++)
        #pragma unroll
        for (int e = 0; e < 4; e++) o[s][e] = 0.f;
    const int ntbase = half * 4;

    for (int kk = 0; kk < 8; kk++) {
        int k0 = kk * 16;
        u32 qh0,qh1,qh2,qh3, ql0,ql1,ql2,ql3;
        ldsm4(qh0,qh1,qh2,qh3, a_addr(sb+SQ_HI, i0, k0, lane));
        ldsm4(ql0,ql1,ql2,ql3, a_addr(sb+SQ_LO, i0, k0, lane));
        const bool doA = (kk <= ib);
        u32 ah0=0,ah1=0,ah2=0,ah3=0, al0=0,al1=0,al2=0,al3=0;
        if (doA) {
            ldsm4(ah0,ah1,ah2,ah3, a_addr(sb+SK_HI, i0, k0, lane));
            ldsm4(al0,al1,al2,al3, a_addr(sb+SK_LO, i0, k0, lane));
        }
        #pragma unroll
        for (int t = 0; t < 4; t++) {
            int nt = ntbase + t;
            u32 sh0,sh1, sl0,sl1;
            ldsm2(sh0,sh1, b_addr(sb+SS_HI, nt*8, k0, lane));
            ldsm2(sl0,sl1, b_addr(sb+SS_LO, nt*8, k0, lane));
            mma16816(o[t], qh0,qh1,qh2,qh3, sh0,sh1);
            mma16816(o[t], qh0,qh1,qh2,qh3, sl0,sl1);
            mma16816(o[t], ql0,ql1,ql2,ql3, sh0,sh1);
            if (doA) {
                u32 vh0,vh1, vl0,vl1;
                ldsm2(vh0,vh1, b_addr(sb+SV_HI, nt*8, k0, lane));
                ldsm2(vl0,vl1, b_addr(sb+SV_LO, nt*8, k0, lane));
                mma16816(o[t], ah0,ah1,ah2,ah3, vh0,vh1);
                mma16816(o[t], ah0,ah1,ah2,ah3, vl0,vl1);
                mma16816(o[t], al0,al1,al2,al3, vh0,vh1);
            }
        }
        if (half == 1) {
            u32 sh0,sh1, sl0,sl1;
            ldsm2(sh0,sh1, b_addr(sb+SS_HI, 64, k0, lane));
            ldsm2(sl0,sl1, b_addr(sb+SS_LO, 64, k0, lane));
            mma16816(o[4], qh0,qh1,qh2,qh3, sh0,sh1);
            mma16816(o[4], qh0,qh1,qh2,qh3, sl0,sl1);
            mma16816(o[4], ql0,ql1,ql2,ql3, sh0,sh1);
            if (doA) {
                u32 vh0,vh1, vl0,vl1;
                ldsm2(vh0,vh1, b_addr(sb+SV_HI, 64, k0, lane));
                ldsm2(vl0,vl1, b_addr(sb+SV_LO, 64, k0, lane));
                mma16816(o[4], ah0,ah1,ah2,ah3, vh0,vh1);
                mma16816(o[4], ah0,ah1,ah2,ah3, vl0,vl1);
                mma16816(o[4], al0,al1,al2,al3, vh0,vh1);
            }
        }
    }

    if (half == 1 && (lane & 3) == 0) {
        rm_s[i0 + (lane >> 2)]     = 1.f / (o[4][0] + EPS_DEN);
        rm_s[i0 + 8 + (lane >> 2)] = 1.f / (o[4][2] + EPS_DEN);
    }
    __syncthreads();
    {
        const int m1 = i0 + (lane >> 2);
        const int m2 = m1 + 8;
        const float inv1 = rm_s[m1];
        const float inv2 = rm_s[m2];
        #pragma unroll
        for (int t = 0; t < 4; t++) {
            int n = (ntbase + t)*8 + 2*(lane & 3);
            float2 t1 = { o[t][0]*inv1, o[t][1]*inv1 };
            float2 t2 = { o[t][2]*inv2, o[t][3]*inv2 };
            *reinterpret_cast<float2*>(outg + (tok0 + m1)*Dd + n) = t1;
            *reinterpret_cast<float2*>(outg + (tok0 + m2)*Dd + n) = t2;
        }
    }
}

// ---------------------------------------------------------------------------

extern "C" void kernel_launch(void* const* d_in, const int* in_sizes, int n_in,
                              void* d_out, int out_size) {
    const float* q  = (const float*)d_in[0];
    const float* k  = (const float*)d_in[1];
    const float* v  = (const float*)d_in[2];
    const float* om = (const float*)d_in[3];
    float* out = (float*)d_out;

    cudaFuncSetAttribute(k_proj_mma, cudaFuncAttributeMaxDynamicSharedMemorySize, SM1T);
    cudaFuncSetAttribute(k_sums_mma, cudaFuncAttributeMaxDynamicSharedMemorySize, SM2T);
    cudaFuncSetAttribute(k_out_mma,  cudaFuncAttributeMaxDynamicSharedMemorySize, SM4T);

    k_proj_mma<<<NBT, 256, SM1T>>>(k, om);
    k_gmax<<<1, 256>>>();
    k_sums_mma<<<NBT, 256, SM2T>>>(v);
    k_scan<<<2048 + 32, 256>>>();
    k_out_mma<<<NBT, 512, SM4T>>>(q, om, v, out);
}